// round 1
// baseline (speedup 1.0000x reference)
#include <cuda_runtime.h>
#include <math.h>
#include <stdint.h>

// Problem constants
#define BSZ 2048
#define XS  256
#define HS  512
#define RS  64
#define MS  128
#define KS  64
#define HID 128    // H/4
#define CAT0 832   // X+H+R
#define XCU 896    // X+H+M
#define GN  1536   // 3H
#define OC  576    // H+R

// ---------------- scratch (device globals; no allocations) ----------------
__device__ __align__(16) float g_xcu [BSZ*XCU];
__device__ __align__(16) float g_base[BSZ*HID];
__device__ __align__(16) float g_keyW[MS*HID];
__device__ __align__(16) float g_head[BSZ*MS];
__device__ __align__(16) float g_ab  [BSZ*2];
__device__             int   g_idx [BSZ];
__device__ __align__(16) float g_r   [BSZ*RS];
__device__ __align__(16) float g_cat0[BSZ*CAT0];
__device__ __align__(16) float g_G   [BSZ*GN];
__device__ __align__(16) float g_P   [BSZ*HS];
__device__ __align__(16) float g_hw  [BSZ*RS];

__device__ __forceinline__ float tanh_fast(float x) {
    float y;
    asm("tanh.approx.f32 %0, %1;" : "=f"(y) : "f"(x));
    return y;
}
__device__ __forceinline__ float sigm(float x) { return 1.f/(1.f+expf(-x)); }
__device__ __forceinline__ float gumbel(float u) {
    return -logf(1e-20f - logf(1e-20f + u));
}

// ---------------- k_xcu: build [x, c, l2n(u_t)] (B x 896) ----------------
__global__ void k_xcu(const float* __restrict__ x, const float* __restrict__ c,
                      const float* __restrict__ u) {
    __shared__ float red[128];
    int b = blockIdx.x, t = threadIdx.x;
    if (t < 128) { float v = u[b*128+t]; red[t] = v*v; }
    __syncthreads();
    for (int s = 64; s > 0; s >>= 1) { if (t < s) red[t] += red[t+s]; __syncthreads(); }
    float inv = 1.f / fmaxf(sqrtf(red[0]), 1e-12f);
    for (int j = t; j < XCU; j += blockDim.x) {
        float v = (j < 256) ? x[b*256+j]
                : (j < 768) ? c[b*512 + (j-256)]
                            : u[b*128 + (j-768)] * inv;
        g_xcu[(size_t)b*XCU + j] = v;
    }
}

// ---------------- k_keyW: keys(128x64) @ W_k(64x128) ----------------
__global__ void k_keyW(const float* __restrict__ keys, const float* __restrict__ W_fc) {
    __shared__ float krow[64];
    int m = blockIdx.x, t = threadIdx.x;
    if (t < 64) krow[t] = keys[m*64 + t];
    __syncthreads();
    float acc = 0.f;
    #pragma unroll 8
    for (int r = 0; r < 64; r++) acc += krow[r] * W_fc[(768+r)*128 + t];
    g_keyW[m*128 + t] = acc;
}

// ------------- k_base: base = xcu @ W_fc[rows 0..767, 896..1023] + b_fc -------------
// tall-skinny, 8 rows per 128-thread block, N=128
__global__ __launch_bounds__(128) void k_base(const float* __restrict__ W_fc,
                                              const float* __restrict__ bfc) {
    __shared__ float Ash[8*XCU];
    int b0 = blockIdx.x * 8, tid = threadIdx.x;
    for (int i = tid; i < 8*XCU; i += 128) Ash[i] = g_xcu[(size_t)b0*XCU + i];
    __syncthreads();
    float acc[8] = {};
    for (int k = 0; k < 768; k++) {
        float wv = W_fc[k*128 + tid];
        #pragma unroll
        for (int r = 0; r < 8; r++) acc[r] += Ash[r*XCU + k] * wv;
    }
    for (int k = 768; k < XCU; k++) {   // u_hat pairs with W_u rows 896..1023
        float wv = W_fc[(k+128)*128 + tid];
        #pragma unroll
        for (int r = 0; r < 8; r++) acc[r] += Ash[r*XCU + k] * wv;
    }
    float bb = bfc[tid];
    #pragma unroll
    for (int r = 0; r < 8; r++) g_base[(size_t)(b0+r)*128 + tid] = acc[r] + bb;
}

// ------------- k_hid: heavy kernel. per (b,m): hid = base + keyW + hmem_row@W_m;
//               head[b,m] = sum_k tanh(hid)*a_k.  Also copies hmem -> out_hmem. -------------
// 2 batches per 256-thread block; W_m, keyW (padded), hmem rows staged in smem.
#define HSTR (128*65)
__global__ __launch_bounds__(256, 1) void k_hid(const float* __restrict__ hmem,
                                                const float* __restrict__ W_fc,
                                                const float* __restrict__ vec_a,
                                                float* __restrict__ out_hmem) {
    extern __shared__ float sm[];
    float* Wm   = sm;                     // 64*128      = 8192
    float* keyW = sm + 8192;              // 128*129     = 16512
    float* hst  = sm + 8192 + 16512;      // 2*128*65    = 16640
    float* bas  = hst + 2*HSTR;           // 2*128       = 256
    float* ash  = bas + 256;              // 128
    int tid = threadIdx.x;
    int b0 = blockIdx.x * 2;

    for (int i = tid; i < 2048; i += 256) {            // W_m = W_fc rows 832..895
        int r = i >> 5, kq = i & 31;
        float4 v = *reinterpret_cast<const float4*>(&W_fc[(832+r)*128 + kq*4]);
        *reinterpret_cast<float4*>(&Wm[r*128 + kq*4]) = v;
    }
    for (int i = tid; i < 16384; i += 256) {           // keyW, pad 129
        int m = i >> 7, k = i & 127;
        keyW[m*129 + k] = g_keyW[i];
    }
    if (tid < 128) ash[tid] = vec_a[tid];
    #pragma unroll
    for (int bl = 0; bl < 2; bl++) {
        int b = b0 + bl;
        if (tid < 128) bas[bl*128 + tid] = g_base[(size_t)b*128 + tid];
        const float4* src = reinterpret_cast<const float4*>(&hmem[(size_t)b*8192]);
        float4*       dst = reinterpret_cast<float4*>(&out_hmem[(size_t)b*8192]);
        for (int i = tid; i < 2048; i += 256) {
            float4 v = src[i];
            dst[i] = v;                                // fused hmem -> new_hmem copy
            int m = i >> 4, r4 = (i & 15) * 4;
            float* p = &hst[bl*HSTR + m*65 + r4];
            p[0] = v.x; p[1] = v.y; p[2] = v.z; p[3] = v.w;
        }
    }
    __syncthreads();

    int m = tid & 127, bl = tid >> 7;
    int b = b0 + bl;
    float hrow[64];
    #pragma unroll
    for (int r = 0; r < 64; r++) hrow[r] = hst[bl*HSTR + m*65 + r];
    const float* kwrow = &keyW[m*129];
    const float* brow  = &bas[bl*128];
    float head = 0.f;
    for (int k0 = 0; k0 < 128; k0 += 8) {
        float acc[8];
        #pragma unroll
        for (int j = 0; j < 8; j++) acc[j] = brow[k0+j] + kwrow[k0+j];
        #pragma unroll
        for (int r = 0; r < 64; r++) {
            float4 w0 = *reinterpret_cast<const float4*>(&Wm[r*128 + k0]);
            float4 w1 = *reinterpret_cast<const float4*>(&Wm[r*128 + k0 + 4]);
            float hv = hrow[r];
            acc[0] += hv*w0.x; acc[1] += hv*w0.y; acc[2] += hv*w0.z; acc[3] += hv*w0.w;
            acc[4] += hv*w1.x; acc[5] += hv*w1.y; acc[6] += hv*w1.z; acc[7] += hv*w1.w;
        }
        #pragma unroll
        for (int j = 0; j < 8; j++) head += tanh_fast(acc[j]) * ash[k0+j];
    }
    g_head[(size_t)b*128 + m] = head;
}

// ------------- k_head_r: l2n(head - 100*prev) + gumbel -> argmax -> gather r -------------
__global__ void k_head_r(const float* __restrict__ prev, const float* __restrict__ nsm,
                         const float* __restrict__ hmem, float* __restrict__ d_out) {
    __shared__ float red[128];
    __shared__ float sv[128];
    __shared__ int   si[128];
    int b = blockIdx.x, t = threadIdx.x;
    float val = g_head[(size_t)b*128 + t] - 100.f * prev[b*128 + t];
    red[t] = val * val;
    __syncthreads();
    for (int s = 64; s > 0; s >>= 1) { if (t < s) red[t] += red[t+s]; __syncthreads(); }
    float norm = fmaxf(sqrtf(red[0]), 1e-12f);
    float z = val / norm + gumbel(nsm[b*128 + t]);
    sv[t] = z; si[t] = t;
    __syncthreads();
    for (int s = 64; s > 0; s >>= 1) {
        if (t < s && sv[t+s] > sv[t]) { sv[t] = sv[t+s]; si[t] = si[t+s]; }
        __syncthreads();
    }
    int best = si[0];
    if (t == 0) g_idx[b] = best;
    if (t < 64) {
        float rv = hmem[((size_t)b*128 + best)*64 + t];
        g_r[b*64 + t] = rv;
        d_out[(size_t)b*OC + 512 + t] = rv;   // output[:,512:576] = r
    }
}

// ---------------- k_cat0: concat0 = [x, h, r] ----------------
__global__ void k_cat0(const float* __restrict__ x, const float* __restrict__ h) {
    int b = blockIdx.x;
    for (int j = threadIdx.x; j < CAT0; j += blockDim.x) {
        float v = (j < 256) ? x[b*256+j]
                : (j < 768) ? h[b*512 + (j-256)]
                            : g_r[b*64 + (j-768)];
        g_cat0[(size_t)b*CAT0 + j] = v;
    }
}

// ---------------- k_ab: alpha/beta = sigmoid((concat0@W1 + b1 + gumbel)*10/3) ----------------
__global__ void k_ab(const float* __restrict__ W1, const float* __restrict__ b1,
                     const float* __restrict__ nsig) {
    int w = threadIdx.x >> 5, lane = threadIdx.x & 31;
    int b = blockIdx.x * 8 + w;
    float s0 = 0.f, s1 = 0.f;
    for (int k = lane; k < CAT0; k += 32) {
        float a = g_cat0[(size_t)b*CAT0 + k];
        s0 += a * W1[k*2];
        s1 += a * W1[k*2 + 1];
    }
    #pragma unroll
    for (int o = 16; o > 0; o >>= 1) {
        s0 += __shfl_down_sync(0xffffffffu, s0, o);
        s1 += __shfl_down_sync(0xffffffffu, s1, o);
    }
    if (lane == 0) {
        const float ST = (float)(10.0/3.0);
        g_ab[b*2]     = sigm((s0 + b1[0] + gumbel(nsig[b*2]))   * ST);
        g_ab[b*2 + 1] = sigm((s1 + b1[1] + gumbel(nsig[b*2+1])) * ST);
    }
}

// ---------------- generic tiled SGEMM (fp32), AMODE=1 applies per-row segment scaling ----------------
template<int BM, int BN, int BK, int TM, int TN, int AMODE>
__global__ void sgemm_k(const float* __restrict__ A, const float* __restrict__ B,
                        float* __restrict__ C, const float* __restrict__ bias,
                        const float* __restrict__ ab, int M, int N, int K) {
    constexpr int TX = BN / TN, TY = BM / TM, NT = TX * TY;
    __shared__ float As[BK * BM];
    __shared__ float Bs[BK * BN];
    int tid = threadIdx.x;
    int tx = tid % TX, ty = tid / TX;
    int m0 = blockIdx.y * BM, n0 = blockIdx.x * BN;
    float acc[TM][TN] = {};

    for (int kt = 0; kt < K; kt += BK) {
        for (int i = tid; i < BM*BK/4; i += NT) {
            int row = i / (BK/4);
            int q   = i % (BK/4);
            int kk  = kt + q*4;
            float4 v = *reinterpret_cast<const float4*>(&A[(size_t)(m0+row)*K + kk]);
            float s = 1.f;
            if (AMODE == 1) {
                if (kk >= 768)      s = ab[(m0+row)*2 + 1];
                else if (kk >= 256) s = ab[(m0+row)*2];
            }
            As[(q*4+0)*BM + row] = v.x * s;
            As[(q*4+1)*BM + row] = v.y * s;
            As[(q*4+2)*BM + row] = v.z * s;
            As[(q*4+3)*BM + row] = v.w * s;
        }
        for (int i = tid; i < BK*BN/4; i += NT) {
            int r  = i / (BN/4);
            int c4 = i % (BN/4);
            float4 v = *reinterpret_cast<const float4*>(&B[(size_t)(kt+r)*N + n0 + c4*4]);
            *reinterpret_cast<float4*>(&Bs[r*BN + c4*4]) = v;
        }
        __syncthreads();
        #pragma unroll
        for (int k = 0; k < BK; k++) {
            float af[TM], bf[TN];
            #pragma unroll
            for (int i = 0; i < TM; i += 4) {
                float4 v = *reinterpret_cast<const float4*>(&As[k*BM + ty*TM + i]);
                af[i] = v.x; af[i+1] = v.y; af[i+2] = v.z; af[i+3] = v.w;
            }
            #pragma unroll
            for (int j = 0; j < TN; j += 4) {
                float4 v = *reinterpret_cast<const float4*>(&Bs[k*BN + tx*TN + j]);
                bf[j] = v.x; bf[j+1] = v.y; bf[j+2] = v.z; bf[j+3] = v.w;
            }
            #pragma unroll
            for (int i = 0; i < TM; i++)
                #pragma unroll
                for (int j = 0; j < TN; j++)
                    acc[i][j] += af[i] * bf[j];
        }
        __syncthreads();
    }
    #pragma unroll
    for (int i = 0; i < TM; i++) {
        #pragma unroll
        for (int j = 0; j < TN; j += 4) {
            float4 v;
            v.x = acc[i][j]   + bias[n0 + tx*TN + j];
            v.y = acc[i][j+1] + bias[n0 + tx*TN + j+1];
            v.z = acc[i][j+2] + bias[n0 + tx*TN + j+2];
            v.w = acc[i][j+3] + bias[n0 + tx*TN + j+3];
            *reinterpret_cast<float4*>(&C[(size_t)(m0 + ty*TM + i)*N + n0 + tx*TN + j]) = v;
        }
    }
}

// ---------------- k_ep: LSTM epilogue -> new_h into output[:, :512] ----------------
__global__ void k_ep(const float* __restrict__ c, float* __restrict__ d_out) {
    int gid = blockIdx.x * blockDim.x + threadIdx.x;   // over B*H
    int b = gid >> 9, j = gid & 511;
    float i_ = g_G[(size_t)b*GN + j];
    float f_ = g_G[(size_t)b*GN + 512 + j];
    float o_ = g_G[(size_t)b*GN + 1024 + j];
    float p  = g_P[(size_t)b*HS + j];
    float nc = c[gid] * sigm(f_ + 1.f) + sigm(i_) * tanhf(p);
    float nh = tanhf(nc) * sigm(o_);
    d_out[(size_t)b*OC + j] = nh;
}

// ---------------- k_hw: h_w = [x, new_h] @ W_fc1 + b_fc1 ----------------
__global__ __launch_bounds__(64) void k_hw(const float* __restrict__ x,
                                           const float* __restrict__ d_out,
                                           const float* __restrict__ Wfc1,
                                           const float* __restrict__ bfc1) {
    __shared__ float Ash[8*768];
    int b0 = blockIdx.x * 8, tid = threadIdx.x;
    for (int i = tid; i < 8*768; i += 64) {
        int r = i / 768, k = i % 768;
        Ash[i] = (k < 256) ? x[(size_t)(b0+r)*256 + k]
                           : d_out[(size_t)(b0+r)*OC + (k-256)];
    }
    __syncthreads();
    float acc[8] = {};
    for (int k = 0; k < 768; k++) {
        float wv = Wfc1[k*64 + tid];
        #pragma unroll
        for (int r = 0; r < 8; r++) acc[r] += Ash[r*768 + k] * wv;
    }
    float bb = bfc1[tid];
    #pragma unroll
    for (int r = 0; r < 8; r++) g_hw[(size_t)(b0+r)*64 + tid] = acc[r] + bb;
}

// ---------------- k_whw: write replaced hmem row ----------------
__global__ void k_whw(const int* __restrict__ memcnt, float* __restrict__ out_hmem) {
    int b = blockIdx.x, t = threadIdx.x;
    int mc = memcnt[0];
    int row = (mc < MS) ? mc : g_idx[b];
    out_hmem[((size_t)b*MS + row)*RS + t] = g_hw[(size_t)b*RS + t];
}

// ---------------- launch ----------------
extern "C" void kernel_launch(void* const* d_in, const int* in_sizes, int n_in,
                              void* d_out, int out_size) {
    const float* x        = (const float*)d_in[0];
    const float* h        = (const float*)d_in[1];
    const float* c        = (const float*)d_in[2];
    const float* hmem     = (const float*)d_in[3];
    const float* u_t      = (const float*)d_in[4];
    const float* prev     = (const float*)d_in[5];
    const float* W_full   = (const float*)d_in[6];
    const float* bias     = (const float*)d_in[7];
    const float* W_full1  = (const float*)d_in[8];
    const float* bias1    = (const float*)d_in[9];
    const float* W_full2  = (const float*)d_in[10];
    const float* bias2    = (const float*)d_in[11];
    const float* keys     = (const float*)d_in[12];
    const float* vec_a    = (const float*)d_in[13];
    const float* W_fc     = (const float*)d_in[14];
    const float* b_fc     = (const float*)d_in[15];
    const float* W_fc1    = (const float*)d_in[16];
    const float* b_fc1    = (const float*)d_in[17];
    const float* noise_sm = (const float*)d_in[18];
    const float* noise_sig= (const float*)d_in[19];
    const int*   memcnt   = (const int*)d_in[20];

    float* out      = (float*)d_out;
    float* out_hmem = out + (size_t)BSZ * OC;

    float *pcat0, *pG, *pP, *pab;
    cudaGetSymbolAddress((void**)&pcat0, g_cat0);
    cudaGetSymbolAddress((void**)&pG,    g_G);
    cudaGetSymbolAddress((void**)&pP,    g_P);
    cudaGetSymbolAddress((void**)&pab,   g_ab);

    cudaFuncSetAttribute(k_hid, cudaFuncAttributeMaxDynamicSharedMemorySize, 170000);
    size_t hid_smem = (size_t)(8192 + 16512 + 2*HSTR + 256 + 128) * sizeof(float);

    k_xcu <<<BSZ, 256>>>(x, c, u_t);
    k_keyW<<<MS, 128>>>(keys, W_fc);
    k_base<<<BSZ/8, 128>>>(W_fc, b_fc);
    k_hid <<<BSZ/2, 256, hid_smem>>>(hmem, W_fc, vec_a, out_hmem);
    k_head_r<<<BSZ, 128>>>(prev, noise_sm, hmem, out);
    k_cat0<<<BSZ, 256>>>(x, h);
    k_ab  <<<BSZ/8, 256>>>(W_full1, bias1, noise_sig);
    sgemm_k<128,128,8,8,8,0><<<dim3(GN/128, BSZ/128), 256>>>(
        pcat0, W_full,  pG, bias,  nullptr, BSZ, GN, CAT0);
    sgemm_k<128, 64,8,8,8,1><<<dim3(HS/64,  BSZ/128), 128>>>(
        pcat0, W_full2, pP, bias2, pab,     BSZ, HS, CAT0);
    k_ep  <<<(BSZ*HS)/256, 256>>>(c, out);
    k_hw  <<<BSZ/8, 64>>>(x, out, W_fc1, b_fc1);
    k_whw <<<BSZ, 64>>>(memcnt, out_hmem);
    (void)in_sizes; (void)n_in; (void)out_size;
}

// round 3
// speedup vs baseline: 1.2749x; 1.2749x over previous
#include <cuda_runtime.h>
#include <cuda_bf16.h>
#include <math.h>
#include <stdint.h>

#define BSZ 2048
#define HS  512
#define RS  64
#define MS  128
#define CAT0 832
#define XCU 896
#define GN  1536
#define OC  576

typedef __nv_bfloat16 bf16;

// ---------------- scratch (device globals; no allocations) ----------------
__device__ __align__(16) float g_xcu  [BSZ*XCU];
__device__ __align__(16) float g_base [BSZ*128];
__device__ __align__(16) float g_keyW [128*128];   // [m][k']
__device__ __align__(16) float g_head [BSZ*MS];
__device__ __align__(16) float g_ab   [BSZ*2];
__device__             int   g_idx  [BSZ];
__device__ __align__(16) float g_r    [BSZ*RS];
__device__ __align__(16) float g_cat0 [BSZ*CAT0];
__device__ __align__(16) float g_G    [BSZ*GN];
__device__ __align__(16) float g_P    [BSZ*HS];
__device__ __align__(16) float g_hw   [BSZ*RS];
__device__ __align__(16) float g_xh   [BSZ*768];
__device__ __align__(16) float g_veca [128];
// bf16 split weights, stored TRANSPOSED [N][K]
__device__ __align__(16) bf16 g_WG_hi[GN*CAT0],  g_WG_lo[GN*CAT0];
__device__ __align__(16) bf16 g_WP_hi[HS*CAT0],  g_WP_lo[HS*CAT0];
__device__ __align__(16) bf16 g_Wb_hi[128*XCU],  g_Wb_lo[128*XCU];
__device__ __align__(16) bf16 g_Ww_hi[64*768],   g_Ww_lo[64*768];
__device__ __align__(16) bf16 g_Wm_hi[128*64],   g_Wm_lo[128*64];

__device__ __forceinline__ float tanh_fast(float x) {
    float y; asm("tanh.approx.f32 %0, %1;" : "=f"(y) : "f"(x)); return y;
}
__device__ __forceinline__ float sigm(float x) { return 1.f/(1.f+expf(-x)); }
__device__ __forceinline__ float gumbel(float u) {
    return -logf(1e-20f - logf(1e-20f + u));
}
__device__ __forceinline__ void split2(float a, float b, uint32_t& hi, uint32_t& lo) {
    __nv_bfloat162 h, l;
    h.x = __float2bfloat16(a); h.y = __float2bfloat16(b);
    l.x = __float2bfloat16(a - __bfloat162float(h.x));
    l.y = __float2bfloat16(b - __bfloat162float(h.y));
    hi = *(uint32_t*)&h; lo = *(uint32_t*)&l;
}
__device__ __forceinline__ void mma_bf16(float* c, const uint32_t* a, uint32_t b0, uint32_t b1) {
    asm volatile("mma.sync.aligned.m16n8k16.row.col.f32.bf16.bf16.f32 "
        "{%0,%1,%2,%3},{%4,%5,%6,%7},{%8,%9},{%0,%1,%2,%3};"
        : "+f"(c[0]), "+f"(c[1]), "+f"(c[2]), "+f"(c[3])
        : "r"(a[0]), "r"(a[1]), "r"(a[2]), "r"(a[3]), "r"(b0), "r"(b1));
}

// ---------------- k_tsplit: transpose + bf16 hi/lo split, 32x32 tiles ----------------
// logical src row k maps to src row (k<split ? k : k+extra); out[n][k] = src[k][n]
__global__ void k_tsplit(const float* __restrict__ src, bf16* __restrict__ dhi,
                         bf16* __restrict__ dlo, int K, int N, int split, int extra) {
    __shared__ float t[32][33];
    int n0 = blockIdx.x*32, k0 = blockIdx.y*32;
    int tx = threadIdx.x & 31, ty = threadIdx.x >> 5;
    for (int r = ty; r < 32; r += 8) {
        int k = k0 + r; int sr = (k < split) ? k : k + extra;
        t[r][tx] = src[(size_t)sr*N + n0 + tx];
    }
    __syncthreads();
    for (int r = ty; r < 32; r += 8) {
        float v = t[tx][r];
        bf16 hi = __float2bfloat16(v);
        size_t o = (size_t)(n0 + r)*K + k0 + tx;
        dhi[o] = hi;
        dlo[o] = __float2bfloat16(v - __bfloat162float(hi));
    }
}

__global__ void k_misc(const float* __restrict__ vec_a) {
    g_veca[threadIdx.x] = vec_a[threadIdx.x];
}

// ---------------- k_xcu: [x, c, l2n(u_t)] ----------------
__global__ void k_xcu(const float* __restrict__ x, const float* __restrict__ c,
                      const float* __restrict__ u) {
    __shared__ float red[128];
    int b = blockIdx.x, t = threadIdx.x;
    if (t < 128) { float v = u[b*128+t]; red[t] = v*v; }
    __syncthreads();
    for (int s = 64; s > 0; s >>= 1) { if (t < s) red[t] += red[t+s]; __syncthreads(); }
    float inv = 1.f / fmaxf(sqrtf(red[0]), 1e-12f);
    for (int j = t; j < XCU; j += blockDim.x) {
        float v = (j < 256) ? x[b*256+j]
                : (j < 768) ? c[b*512 + (j-256)]
                            : u[b*128 + (j-768)] * inv;
        g_xcu[(size_t)b*XCU + j] = v;
    }
}

// ---------------- k_keyW: keys(128x64) @ W_k -> g_keyW[m][k'] ----------------
__global__ void k_keyW(const float* __restrict__ keys, const float* __restrict__ W_fc) {
    __shared__ float krow[64];
    int m = blockIdx.x, t = threadIdx.x;
    if (t < 64) krow[t] = keys[m*64 + t];
    __syncthreads();
    float acc = 0.f;
    #pragma unroll 8
    for (int r = 0; r < 64; r++) acc += krow[r] * W_fc[(768+r)*128 + t];
    g_keyW[m*128 + t] = acc;
}

// ---------------- generic warp-MMA GEMM, bf16 3-split ----------------
template<int WM, int WN, int MF, int NF, int AMODE>
__global__ __launch_bounds__(WM*WN*32) void mgemm(
    const float* __restrict__ A, const bf16* __restrict__ BT_hi,
    const bf16* __restrict__ BT_lo, float* __restrict__ C,
    const float* __restrict__ bias, const float* __restrict__ ab,
    int M, int N, int K) {
    constexpr int BK = 32, LDA = 40;
    constexpr int BM = WM*MF*16, BN = WN*NF*8, NT = WM*WN*32;
    __shared__ bf16 As_hi[BM*LDA], As_lo[BM*LDA], Bs_hi[BN*LDA], Bs_lo[BN*LDA];
    int tid = threadIdx.x;
    int w = tid >> 5, lane = tid & 31, g = lane >> 2, tg = lane & 3;
    int wm = w / WN, wn = w % WN;
    int m0 = blockIdx.y*BM, n0 = blockIdx.x*BN;
    float c[MF][NF][4] = {};

    for (int kt = 0; kt < K; kt += BK) {
        for (int i = tid; i < BM*BK/4; i += NT) {
            int row = i/(BK/4), q = i%(BK/4);
            float4 v = *(const float4*)&A[(size_t)(m0+row)*K + kt + q*4];
            if (AMODE == 1) {
                float s = (kt >= 768) ? ab[(m0+row)*2+1] : (kt >= 256) ? ab[(m0+row)*2] : 1.f;
                v.x *= s; v.y *= s; v.z *= s; v.w *= s;
            }
            uint32_t h0, l0, h1, l1;
            split2(v.x, v.y, h0, l0);
            split2(v.z, v.w, h1, l1);
            uint2 hh; hh.x = h0; hh.y = h1;
            uint2 ll; ll.x = l0; ll.y = l1;
            *(uint2*)&As_hi[row*LDA + q*4] = hh;
            *(uint2*)&As_lo[row*LDA + q*4] = ll;
        }
        for (int i = tid; i < BN*BK/8; i += NT) {
            int r = i/(BK/8), q = i%(BK/8);
            *(uint4*)&Bs_hi[r*LDA + q*8] = *(const uint4*)&BT_hi[(size_t)(n0+r)*K + kt + q*8];
            *(uint4*)&Bs_lo[r*LDA + q*8] = *(const uint4*)&BT_lo[(size_t)(n0+r)*K + kt + q*8];
        }
        __syncthreads();
        #pragma unroll
        for (int k0 = 0; k0 < BK; k0 += 16) {
            uint32_t ah[MF][4], al[MF][4];
            #pragma unroll
            for (int mf = 0; mf < MF; mf++) {
                int r0 = wm*MF*16 + mf*16 + g;
                ah[mf][0] = *(uint32_t*)&As_hi[r0*LDA + k0 + 2*tg];
                ah[mf][1] = *(uint32_t*)&As_hi[(r0+8)*LDA + k0 + 2*tg];
                ah[mf][2] = *(uint32_t*)&As_hi[r0*LDA + k0 + 8 + 2*tg];
                ah[mf][3] = *(uint32_t*)&As_hi[(r0+8)*LDA + k0 + 8 + 2*tg];
                al[mf][0] = *(uint32_t*)&As_lo[r0*LDA + k0 + 2*tg];
                al[mf][1] = *(uint32_t*)&As_lo[(r0+8)*LDA + k0 + 2*tg];
                al[mf][2] = *(uint32_t*)&As_lo[r0*LDA + k0 + 8 + 2*tg];
                al[mf][3] = *(uint32_t*)&As_lo[(r0+8)*LDA + k0 + 8 + 2*tg];
            }
            #pragma unroll
            for (int nf = 0; nf < NF; nf++) {
                int nb = wn*NF*8 + nf*8 + g;
                uint32_t bh0 = *(uint32_t*)&Bs_hi[nb*LDA + k0 + 2*tg];
                uint32_t bh1 = *(uint32_t*)&Bs_hi[nb*LDA + k0 + 8 + 2*tg];
                uint32_t bl0 = *(uint32_t*)&Bs_lo[nb*LDA + k0 + 2*tg];
                uint32_t bl1 = *(uint32_t*)&Bs_lo[nb*LDA + k0 + 8 + 2*tg];
                #pragma unroll
                for (int mf = 0; mf < MF; mf++) {
                    mma_bf16(c[mf][nf], ah[mf], bh0, bh1);
                    mma_bf16(c[mf][nf], al[mf], bh0, bh1);
                    mma_bf16(c[mf][nf], ah[mf], bl0, bl1);
                }
            }
        }
        __syncthreads();
    }
    #pragma unroll
    for (int mf = 0; mf < MF; mf++) {
        int r0 = m0 + wm*MF*16 + mf*16 + g;
        #pragma unroll
        for (int nf = 0; nf < NF; nf++) {
            int cb = n0 + wn*NF*8 + nf*8 + 2*tg;
            C[(size_t)r0*N + cb]       = c[mf][nf][0] + bias[cb];
            C[(size_t)r0*N + cb + 1]   = c[mf][nf][1] + bias[cb+1];
            C[(size_t)(r0+8)*N + cb]   = c[mf][nf][2] + bias[cb];
            C[(size_t)(r0+8)*N + cb+1] = c[mf][nf][3] + bias[cb+1];
        }
    }
}

// ---------------- k_hid_mma: per-batch 128x128x64 MMA + fused head epilogue + hmem copy ----
// WM=2, WN=4, MF=4, NF=4 -> 128x128 tile, K=64 single tile, LDA=72
#define HID_SMEM 140800
__global__ __launch_bounds__(256) void k_hid_mma(const float* __restrict__ hmem,
                                                 float* __restrict__ out_hmem) {
    extern __shared__ char dsm[];
    bf16* As_hi = (bf16*)dsm;                 // 128*72
    bf16* As_lo = As_hi + 9216;
    bf16* Bs_hi = As_lo + 9216;
    bf16* Bs_lo = Bs_hi + 9216;
    float* s_keyW = (float*)(dsm + 73728);    // 128*128
    float* s_base = (float*)(dsm + 139264);
    float* s_veca = s_base + 128;
    float* s_head = s_veca + 128;
    const int LDA = 72;
    int tid = threadIdx.x;
    int w = tid >> 5, lane = tid & 31, g = lane >> 2, tg = lane & 3;
    int wm = w >> 2, wn = w & 3;
    int b = blockIdx.x;

    // loaders
    const float4* src = (const float4*)(hmem + (size_t)b*8192);
    float4*       dst = (float4*)(out_hmem + (size_t)b*8192);
    for (int i = tid; i < 2048; i += 256) {
        float4 v = src[i];
        dst[i] = v;
        int row = i >> 4, c4 = (i & 15) * 4;
        uint32_t h0, l0, h1, l1;
        split2(v.x, v.y, h0, l0);
        split2(v.z, v.w, h1, l1);
        uint2 hh; hh.x = h0; hh.y = h1;
        uint2 ll; ll.x = l0; ll.y = l1;
        *(uint2*)&As_hi[row*LDA + c4] = hh;
        *(uint2*)&As_lo[row*LDA + c4] = ll;
    }
    for (int i = tid; i < 1024; i += 256) {
        int r = i >> 3, q = i & 7;
        *(uint4*)&Bs_hi[r*LDA + q*8] = *(const uint4*)&g_Wm_hi[r*64 + q*8];
        *(uint4*)&Bs_lo[r*LDA + q*8] = *(const uint4*)&g_Wm_lo[r*64 + q*8];
    }
    for (int i = tid; i < 4096; i += 256)
        *(float4*)&s_keyW[i*4] = *(const float4*)&g_keyW[i*4];
    if (tid < 128) {
        s_base[tid] = g_base[(size_t)b*128 + tid];
        s_veca[tid] = g_veca[tid];
        s_head[tid] = 0.f;
    }
    __syncthreads();

    float c[4][4][4] = {};
    #pragma unroll
    for (int k0 = 0; k0 < 64; k0 += 16) {
        uint32_t ah[4][4], al[4][4];
        #pragma unroll
        for (int mf = 0; mf < 4; mf++) {
            int r0 = wm*64 + mf*16 + g;
            ah[mf][0] = *(uint32_t*)&As_hi[r0*LDA + k0 + 2*tg];
            ah[mf][1] = *(uint32_t*)&As_hi[(r0+8)*LDA + k0 + 2*tg];
            ah[mf][2] = *(uint32_t*)&As_hi[r0*LDA + k0 + 8 + 2*tg];
            ah[mf][3] = *(uint32_t*)&As_hi[(r0+8)*LDA + k0 + 8 + 2*tg];
            al[mf][0] = *(uint32_t*)&As_lo[r0*LDA + k0 + 2*tg];
            al[mf][1] = *(uint32_t*)&As_lo[(r0+8)*LDA + k0 + 2*tg];
            al[mf][2] = *(uint32_t*)&As_lo[r0*LDA + k0 + 8 + 2*tg];
            al[mf][3] = *(uint32_t*)&As_lo[(r0+8)*LDA + k0 + 8 + 2*tg];
        }
        #pragma unroll
        for (int nf = 0; nf < 4; nf++) {
            int nb = wn*32 + nf*8 + g;
            uint32_t bh0 = *(uint32_t*)&Bs_hi[nb*LDA + k0 + 2*tg];
            uint32_t bh1 = *(uint32_t*)&Bs_hi[nb*LDA + k0 + 8 + 2*tg];
            uint32_t bl0 = *(uint32_t*)&Bs_lo[nb*LDA + k0 + 2*tg];
            uint32_t bl1 = *(uint32_t*)&Bs_lo[nb*LDA + k0 + 8 + 2*tg];
            #pragma unroll
            for (int mf = 0; mf < 4; mf++) {
                mma_bf16(c[mf][nf], ah[mf], bh0, bh1);
                mma_bf16(c[mf][nf], al[mf], bh0, bh1);
                mma_bf16(c[mf][nf], ah[mf], bl0, bl1);
            }
        }
    }

    // epilogue: head[row] += tanh(c + base[col] + keyW[row][col]) * veca[col]
    #pragma unroll
    for (int mf = 0; mf < 4; mf++) {
        int r0 = wm*64 + mf*16 + g, r1 = r0 + 8;
        float hs0 = 0.f, hs1 = 0.f;
        #pragma unroll
        for (int nf = 0; nf < 4; nf++) {
            int cb = wn*32 + nf*8 + 2*tg;
            float v;
            v = c[mf][nf][0] + s_base[cb]   + s_keyW[r0*128 + cb];   hs0 += tanh_fast(v)*s_veca[cb];
            v = c[mf][nf][1] + s_base[cb+1] + s_keyW[r0*128 + cb+1]; hs0 += tanh_fast(v)*s_veca[cb+1];
            v = c[mf][nf][2] + s_base[cb]   + s_keyW[r1*128 + cb];   hs1 += tanh_fast(v)*s_veca[cb];
            v = c[mf][nf][3] + s_base[cb+1] + s_keyW[r1*128 + cb+1]; hs1 += tanh_fast(v)*s_veca[cb+1];
        }
        atomicAdd(&s_head[r0], hs0);
        atomicAdd(&s_head[r1], hs1);
    }
    __syncthreads();
    if (tid < 128) g_head[(size_t)b*128 + tid] = s_head[tid];
}

// ---------------- k_head_r ----------------
__global__ void k_head_r(const float* __restrict__ prev, const float* __restrict__ nsm,
                         const float* __restrict__ hmem, float* __restrict__ d_out) {
    __shared__ float red[128];
    __shared__ float sv[128];
    __shared__ int   si[128];
    int b = blockIdx.x, t = threadIdx.x;
    float val = g_head[(size_t)b*128 + t] - 100.f * prev[b*128 + t];
    red[t] = val * val;
    __syncthreads();
    for (int s = 64; s > 0; s >>= 1) { if (t < s) red[t] += red[t+s]; __syncthreads(); }
    float norm = fmaxf(sqrtf(red[0]), 1e-12f);
    float z = val / norm + gumbel(nsm[b*128 + t]);
    sv[t] = z; si[t] = t;
    __syncthreads();
    for (int s = 64; s > 0; s >>= 1) {
        if (t < s && sv[t+s] > sv[t]) { sv[t] = sv[t+s]; si[t] = si[t+s]; }
        __syncthreads();
    }
    int best = si[0];
    if (t == 0) g_idx[b] = best;
    if (t < 64) {
        float rv = hmem[((size_t)b*128 + best)*64 + t];
        g_r[b*64 + t] = rv;
        d_out[(size_t)b*OC + 512 + t] = rv;
    }
}

// ---------------- k_cat0 ----------------
__global__ void k_cat0(const float* __restrict__ x, const float* __restrict__ h) {
    int b = blockIdx.x;
    for (int j = threadIdx.x; j < CAT0; j += blockDim.x) {
        float v = (j < 256) ? x[b*256+j]
                : (j < 768) ? h[b*512 + (j-256)]
                            : g_r[b*64 + (j-768)];
        g_cat0[(size_t)b*CAT0 + j] = v;
        if (j < 256) g_xh[(size_t)b*768 + j] = v;
    }
}

// ---------------- k_ab ----------------
__global__ void k_ab(const float* __restrict__ W1, const float* __restrict__ b1,
                     const float* __restrict__ nsig) {
    int w = threadIdx.x >> 5, lane = threadIdx.x & 31;
    int b = blockIdx.x * 8 + w;
    float s0 = 0.f, s1 = 0.f;
    for (int k = lane; k < CAT0; k += 32) {
        float a = g_cat0[(size_t)b*CAT0 + k];
        s0 += a * W1[k*2];
        s1 += a * W1[k*2 + 1];
    }
    #pragma unroll
    for (int o = 16; o > 0; o >>= 1) {
        s0 += __shfl_down_sync(0xffffffffu, s0, o);
        s1 += __shfl_down_sync(0xffffffffu, s1, o);
    }
    if (lane == 0) {
        const float ST = (float)(10.0/3.0);
        g_ab[b*2]     = sigm((s0 + b1[0] + gumbel(nsig[b*2]))   * ST);
        g_ab[b*2 + 1] = sigm((s1 + b1[1] + gumbel(nsig[b*2+1])) * ST);
    }
}

// ---------------- k_ep: LSTM epilogue ----------------
__global__ void k_ep(const float* __restrict__ c, float* __restrict__ d_out) {
    int gid = blockIdx.x * blockDim.x + threadIdx.x;
    int b = gid >> 9, j = gid & 511;
    float i_ = g_G[(size_t)b*GN + j];
    float f_ = g_G[(size_t)b*GN + 512 + j];
    float o_ = g_G[(size_t)b*GN + 1024 + j];
    float p  = g_P[(size_t)b*HS + j];
    float nc = c[gid] * sigm(f_ + 1.f) + sigm(i_) * tanhf(p);
    float nh = tanhf(nc) * sigm(o_);
    d_out[(size_t)b*OC + j] = nh;
    g_xh[(size_t)b*768 + 256 + j] = nh;
}

// ---------------- k_whw ----------------
__global__ void k_whw(const int* __restrict__ memcnt, float* __restrict__ out_hmem) {
    int b = blockIdx.x, t = threadIdx.x;
    int mc = memcnt[0];
    int row = (mc < MS) ? mc : g_idx[b];
    out_hmem[((size_t)b*MS + row)*RS + t] = g_hw[(size_t)b*RS + t];
}

// ---------------- launch ----------------
extern "C" void kernel_launch(void* const* d_in, const int* in_sizes, int n_in,
                              void* d_out, int out_size) {
    const float* x        = (const float*)d_in[0];
    const float* h        = (const float*)d_in[1];
    const float* c        = (const float*)d_in[2];
    const float* hmem     = (const float*)d_in[3];
    const float* u_t      = (const float*)d_in[4];
    const float* prev     = (const float*)d_in[5];
    const float* W_full   = (const float*)d_in[6];
    const float* bias     = (const float*)d_in[7];
    const float* W_full1  = (const float*)d_in[8];
    const float* bias1    = (const float*)d_in[9];
    const float* W_full2  = (const float*)d_in[10];
    const float* bias2    = (const float*)d_in[11];
    const float* keys     = (const float*)d_in[12];
    const float* vec_a    = (const float*)d_in[13];
    const float* W_fc     = (const float*)d_in[14];
    const float* b_fc     = (const float*)d_in[15];
    const float* W_fc1    = (const float*)d_in[16];
    const float* b_fc1    = (const float*)d_in[17];
    const float* noise_sm = (const float*)d_in[18];
    const float* noise_sig= (const float*)d_in[19];
    const int*   memcnt   = (const int*)d_in[20];

    float* out      = (float*)d_out;
    float* out_hmem = out + (size_t)BSZ * OC;

    float *pcat0, *pG, *pP, *pab, *pxcu, *pbase, *pxh, *phw;
    bf16 *pWGh, *pWGl, *pWPh, *pWPl, *pWbh, *pWbl, *pWwh, *pWwl;
    cudaGetSymbolAddress((void**)&pcat0, g_cat0);
    cudaGetSymbolAddress((void**)&pG,    g_G);
    cudaGetSymbolAddress((void**)&pP,    g_P);
    cudaGetSymbolAddress((void**)&pab,   g_ab);
    cudaGetSymbolAddress((void**)&pxcu,  g_xcu);
    cudaGetSymbolAddress((void**)&pbase, g_base);
    cudaGetSymbolAddress((void**)&pxh,   g_xh);
    cudaGetSymbolAddress((void**)&phw,   g_hw);
    cudaGetSymbolAddress((void**)&pWGh,  g_WG_hi);
    cudaGetSymbolAddress((void**)&pWGl,  g_WG_lo);
    cudaGetSymbolAddress((void**)&pWPh,  g_WP_hi);
    cudaGetSymbolAddress((void**)&pWPl,  g_WP_lo);
    cudaGetSymbolAddress((void**)&pWbh,  g_Wb_hi);
    cudaGetSymbolAddress((void**)&pWbl,  g_Wb_lo);
    cudaGetSymbolAddress((void**)&pWwh,  g_Ww_hi);
    cudaGetSymbolAddress((void**)&pWwl,  g_Ww_lo);
    bf16 *pWmh, *pWml;
    cudaGetSymbolAddress((void**)&pWmh,  g_Wm_hi);
    cudaGetSymbolAddress((void**)&pWml,  g_Wm_lo);

    cudaFuncSetAttribute(k_hid_mma, cudaFuncAttributeMaxDynamicSharedMemorySize, HID_SMEM);

    // weight prep (bf16 split, transposed)
    k_tsplit<<<dim3(GN/32,  CAT0/32), 256>>>(W_full,          pWGh, pWGl, CAT0, GN,  CAT0, 0);
    k_tsplit<<<dim3(HS/32,  CAT0/32), 256>>>(W_full2,         pWPh, pWPl, CAT0, HS,  CAT0, 0);
    k_tsplit<<<dim3(128/32, XCU/32),  256>>>(W_fc,            pWbh, pWbl, XCU,  128, 768,  128);
    k_tsplit<<<dim3(64/32,  768/32),  256>>>(W_fc1,           pWwh, pWwl, 768,  64,  768,  0);
    k_tsplit<<<dim3(128/32, 64/32),   256>>>(W_fc + 832*128,  pWmh, pWml, 64,   128, 64,   0);
    k_misc<<<1, 128>>>(vec_a);
    k_keyW<<<MS, 128>>>(keys, W_fc);
    k_xcu <<<BSZ, 256>>>(x, c, u_t);

    // base = xcu @ Wb + b_fc   (2048 x 128 x 896)
    mgemm<2,4,2,4,0><<<dim3(1, BSZ/64), 256>>>(pxcu, pWbh, pWbl, pbase, b_fc, nullptr, BSZ, 128, XCU);
    k_hid_mma<<<BSZ, 256, HID_SMEM>>>(hmem, out_hmem);
    k_head_r<<<BSZ, 128>>>(prev, noise_sm, hmem, out);
    k_cat0<<<BSZ, 256>>>(x, h);
    k_ab  <<<BSZ/8, 256>>>(W_full1, bias1, noise_sig);
    // G = cat0 @ W_full + bias   (2048 x 1536 x 832)
    mgemm<2,4,4,4,0><<<dim3(GN/128, BSZ/128), 256>>>(pcat0, pWGh, pWGl, pG, bias, nullptr, BSZ, GN, CAT0);
    // P = (cat0*scale) @ W_full2 + bias2   (2048 x 512 x 832)
    mgemm<2,4,4,4,1><<<dim3(HS/128, BSZ/128), 256>>>(pcat0, pWPh, pWPl, pP, bias2, pab, BSZ, HS, CAT0);
    k_ep  <<<(BSZ*HS)/256, 256>>>(c, out);
    // h_w = [x, new_h] @ W_fc1 + b_fc1   (2048 x 64 x 768)
    mgemm<2,2,1,4,0><<<dim3(1, BSZ/32), 128>>>(pxh, pWwh, pWwl, phw, b_fc1, nullptr, BSZ, 64, 768);
    k_whw <<<BSZ, 64>>>(memcnt, out_hmem);
    (void)in_sizes; (void)n_in; (void)out_size;
}

// round 4
// speedup vs baseline: 2.0208x; 1.5851x over previous
#include <cuda_runtime.h>
#include <cuda_bf16.h>
#include <math.h>
#include <stdint.h>

#define BSZ 2048
#define HS  512
#define RS  64
#define MS  128
#define CAT0 832
#define XCU 896
#define GN  1536
#define OC  576

typedef __nv_bfloat16 bf16;

// ---------------- scratch (device globals; no allocations) ----------------
__device__ __align__(16) float g_base [BSZ*128];
__device__ __align__(16) float g_keyW [128*128];   // [m][k']
__device__ __align__(16) float g_head [BSZ*MS];
__device__ __align__(16) float g_ab   [BSZ*2];
__device__             int   g_idx  [BSZ];
__device__ __align__(16) float g_r    [BSZ*RS];
__device__ __align__(16) float g_G    [BSZ*GN];
__device__ __align__(16) float g_P    [BSZ*HS];
__device__ __align__(16) float g_hw   [BSZ*RS];
__device__ __align__(16) float g_veca [128];
__device__ __align__(16) float g_uinv [BSZ];
// bf16 split weights, TRANSPOSED [N][K]
__device__ __align__(16) bf16 g_WG_hi[GN*CAT0],  g_WG_lo[GN*CAT0];
__device__ __align__(16) bf16 g_WP_hi[HS*CAT0],  g_WP_lo[HS*CAT0];
__device__ __align__(16) bf16 g_Wb_hi[128*XCU];
__device__ __align__(16) bf16 g_Ww_hi[64*768],   g_Ww_lo[64*768];
__device__ __align__(16) bf16 g_Wm_hi[128*64];

__device__ __forceinline__ float tanh_fast(float x) {
    float y; asm("tanh.approx.f32 %0, %1;" : "=f"(y) : "f"(x)); return y;
}
__device__ __forceinline__ float sigm(float x) { return 1.f/(1.f+expf(-x)); }
__device__ __forceinline__ float gumbel(float u) {
    return -logf(1e-20f - logf(1e-20f + u));
}
__device__ __forceinline__ void split2(float a, float b, uint32_t& hi, uint32_t& lo) {
    __nv_bfloat162 h, l;
    h.x = __float2bfloat16(a); h.y = __float2bfloat16(b);
    l.x = __float2bfloat16(a - __bfloat162float(h.x));
    l.y = __float2bfloat16(b - __bfloat162float(h.y));
    hi = *(uint32_t*)&h; lo = *(uint32_t*)&l;
}
__device__ __forceinline__ uint32_t pack_hi2(float a, float b) {
    __nv_bfloat162 h; h.x = __float2bfloat16(a); h.y = __float2bfloat16(b);
    return *(uint32_t*)&h;
}
__device__ __forceinline__ void mma_bf16(float* c, const uint32_t* a, uint32_t b0, uint32_t b1) {
    asm volatile("mma.sync.aligned.m16n8k16.row.col.f32.bf16.bf16.f32 "
        "{%0,%1,%2,%3},{%4,%5,%6,%7},{%8,%9},{%0,%1,%2,%3};"
        : "+f"(c[0]), "+f"(c[1]), "+f"(c[2]), "+f"(c[3])
        : "r"(a[0]), "r"(a[1]), "r"(a[2]), "r"(a[3]), "r"(b0), "r"(b1));
}
#define LDSM_X4(r, addr) \
    asm volatile("ldmatrix.sync.aligned.m8n8.x4.shared.b16 {%0,%1,%2,%3}, [%4];" \
        : "=r"((r)[0]), "=r"((r)[1]), "=r"((r)[2]), "=r"((r)[3]) : "r"(addr))

// ---------------- k_prep: all weight splits + keyW + uinv + veca in one kernel ----------------
__device__ void tsplit_tile(const float* __restrict__ src, bf16* __restrict__ dhi,
                            bf16* __restrict__ dlo, int K, int N, int split, int extra,
                            int tile, int tid) {
    __shared__ float t[32][33];
    int nt = N/32;
    int n0 = (tile % nt)*32, k0 = (tile / nt)*32;
    int tx = tid & 31, ty = tid >> 5;
    for (int r = ty; r < 32; r += 8) {
        int k = k0 + r; int sr = (k < split) ? k : k + extra;
        t[r][tx] = src[(size_t)sr*N + n0 + tx];
    }
    __syncthreads();
    for (int r = ty; r < 32; r += 8) {
        float v = t[tx][r];
        bf16 hi = __float2bfloat16(v);
        size_t o = (size_t)(n0 + r)*K + k0 + tx;
        dhi[o] = hi;
        if (dlo) dlo[o] = __float2bfloat16(v - __bfloat162float(hi));
    }
}

#define T_WG 1248
#define T_WP (T_WG + 416)
#define T_WB (T_WP + 112)
#define T_WW (T_WB + 48)
#define T_WM (T_WW + 8)
#define T_KW (T_WM + 64)
#define T_UN (T_KW + 256)
#define T_ALL (T_UN + 1)

__global__ __launch_bounds__(256) void k_prep(
    const float* __restrict__ W_full, const float* __restrict__ W_full2,
    const float* __restrict__ W_fc,   const float* __restrict__ W_fc1,
    const float* __restrict__ keys,   const float* __restrict__ vec_a,
    const float* __restrict__ u) {
    int blk = blockIdx.x, tid = threadIdx.x;
    if (blk < T_WG) {
        tsplit_tile(W_full, g_WG_hi, g_WG_lo, CAT0, GN, CAT0, 0, blk, tid);
    } else if (blk < T_WP) {
        tsplit_tile(W_full2, g_WP_hi, g_WP_lo, CAT0, HS, CAT0, 0, blk - T_WG, tid);
    } else if (blk < T_WB) {
        tsplit_tile(W_fc, g_Wb_hi, nullptr, XCU, 128, 768, 128, blk - T_WP, tid);
    } else if (blk < T_WW) {
        tsplit_tile(W_fc1, g_Ww_hi, g_Ww_lo, 768, 64, 768, 0, blk - T_WB, tid);
    } else if (blk < T_WM) {
        tsplit_tile(W_fc + 832*128, g_Wm_hi, nullptr, 64, 128, 64, 0, blk - T_WW, tid);
    } else if (blk < T_KW) {
        // keyW: 2 m-rows per block
        __shared__ float krow[2][64];
        int sub = tid >> 7, t = tid & 127;
        int m = (blk - T_WM)*2 + sub;
        if (t < 64) krow[sub][t] = keys[m*64 + t];
        __syncthreads();
        float acc = 0.f;
        #pragma unroll 8
        for (int r = 0; r < 64; r++) acc += krow[sub][r] * W_fc[(768+r)*128 + t];
        g_keyW[m*128 + t] = acc;
    } else if (blk < T_UN) {
        int w = tid >> 5, lane = tid & 31;
        int b = (blk - T_KW)*8 + w;
        float s = 0.f;
        #pragma unroll
        for (int j = lane; j < 128; j += 32) { float v = u[b*128+j]; s += v*v; }
        #pragma unroll
        for (int o = 16; o > 0; o >>= 1) s += __shfl_down_sync(0xffffffffu, s, o);
        if (lane == 0) g_uinv[b] = 1.f / fmaxf(sqrtf(s), 1e-12f);
    } else {
        if (tid < 128) g_veca[tid] = vec_a[tid];
    }
}

// ---------------- generic warp-MMA GEMM with fused A gather ----------------
// SRC: 1=[x,h,r] (CAT0), 2=[x,c,u*uinv] (XCU), 3=[x,new_h from d_out] (768)
// SCALE: per-segment alpha/beta scaling from aux (=g_ab) for SRC 1
template<int WM, int WN, int MF, int NF, int SRC, int SCALE, int PASSES>
__global__ __launch_bounds__(WM*WN*32) void mgemm(
    const float* __restrict__ p0, const float* __restrict__ p1,
    const float* __restrict__ p2, const float* __restrict__ aux,
    const bf16* __restrict__ BT_hi, const bf16* __restrict__ BT_lo,
    float* __restrict__ C, const float* __restrict__ bias, int N, int K) {
    constexpr int BK = 32, LDA = 40;
    constexpr int BM = WM*MF*16, BN = WN*NF*8, NT = WM*WN*32;
    __shared__ __align__(16) bf16 As_hi[BM*LDA];
    __shared__ __align__(16) bf16 As_lo[(PASSES > 1) ? BM*LDA : 8];
    __shared__ __align__(16) bf16 Bs_hi[BN*LDA];
    __shared__ __align__(16) bf16 Bs_lo[(PASSES > 1) ? BN*LDA : 8];
    int tid = threadIdx.x;
    int w = tid >> 5, lane = tid & 31, g = lane >> 2, tg = lane & 3;
    int wm = w / WN, wn = w % WN;
    int m0 = blockIdx.y*BM, n0 = blockIdx.x*BN;
    float c[MF][NF][4] = {};

    uint32_t a_lane_off = (uint32_t)(((((lane>>3)&1)*8 + (lane&7))*LDA + (lane>>4)*8) * 2);
    uint32_t as_hi_base = (uint32_t)__cvta_generic_to_shared(As_hi) + (uint32_t)(wm*MF*16*LDA*2) + a_lane_off;
    uint32_t as_lo_base = (uint32_t)__cvta_generic_to_shared(As_lo) + (uint32_t)(wm*MF*16*LDA*2) + a_lane_off;

    for (int kt = 0; kt < K; kt += BK) {
        for (int i = tid; i < BM*BK/4; i += NT) {
            int row = i/(BK/4), q = i%(BK/4);
            int gr = m0 + row;
            int kk = kt + q*4;
            float4 v;
            if (SRC == 1) {
                if (kk < 256)      v = *(const float4*)&p0[(size_t)gr*256 + kk];
                else if (kk < 768) v = *(const float4*)&p1[(size_t)gr*512 + kk-256];
                else               v = *(const float4*)&p2[(size_t)gr*64  + kk-768];
                if (SCALE) {
                    float s = (kk >= 768) ? aux[gr*2+1] : (kk >= 256) ? aux[gr*2] : 1.f;
                    v.x *= s; v.y *= s; v.z *= s; v.w *= s;
                }
            } else if (SRC == 2) {
                if (kk < 256)      v = *(const float4*)&p0[(size_t)gr*256 + kk];
                else if (kk < 768) v = *(const float4*)&p1[(size_t)gr*512 + kk-256];
                else {
                    v = *(const float4*)&p2[(size_t)gr*128 + kk-768];
                    float s = aux[gr];
                    v.x *= s; v.y *= s; v.z *= s; v.w *= s;
                }
            } else {
                if (kk < 256)      v = *(const float4*)&p0[(size_t)gr*256 + kk];
                else               v = *(const float4*)&p1[(size_t)gr*OC + kk-256];
            }
            if (PASSES > 1) {
                uint32_t h0, l0, h1, l1;
                split2(v.x, v.y, h0, l0);
                split2(v.z, v.w, h1, l1);
                uint2 hh; hh.x = h0; hh.y = h1;
                uint2 ll; ll.x = l0; ll.y = l1;
                *(uint2*)&As_hi[row*LDA + q*4] = hh;
                *(uint2*)&As_lo[row*LDA + q*4] = ll;
            } else {
                uint2 hh; hh.x = pack_hi2(v.x, v.y); hh.y = pack_hi2(v.z, v.w);
                *(uint2*)&As_hi[row*LDA + q*4] = hh;
            }
        }
        for (int i = tid; i < BN*BK/8; i += NT) {
            int r = i/(BK/8), q = i%(BK/8);
            *(uint4*)&Bs_hi[r*LDA + q*8] = *(const uint4*)&BT_hi[(size_t)(n0+r)*K + kt + q*8];
            if (PASSES > 1)
                *(uint4*)&Bs_lo[r*LDA + q*8] = *(const uint4*)&BT_lo[(size_t)(n0+r)*K + kt + q*8];
        }
        __syncthreads();
        #pragma unroll
        for (int k0 = 0; k0 < BK; k0 += 16) {
            uint32_t ah[MF][4], al[MF][4];
            #pragma unroll
            for (int mf = 0; mf < MF; mf++) {
                LDSM_X4(ah[mf], as_hi_base + (uint32_t)((mf*16*LDA + k0)*2));
                if (PASSES > 1)
                    LDSM_X4(al[mf], as_lo_base + (uint32_t)((mf*16*LDA + k0)*2));
            }
            #pragma unroll
            for (int nf = 0; nf < NF; nf++) {
                int nb = wn*NF*8 + nf*8 + g;
                uint32_t bh0 = *(uint32_t*)&Bs_hi[nb*LDA + k0 + 2*tg];
                uint32_t bh1 = *(uint32_t*)&Bs_hi[nb*LDA + k0 + 8 + 2*tg];
                #pragma unroll
                for (int mf = 0; mf < MF; mf++) mma_bf16(c[mf][nf], ah[mf], bh0, bh1);
                if (PASSES > 1) {
                    uint32_t bl0 = *(uint32_t*)&Bs_lo[nb*LDA + k0 + 2*tg];
                    uint32_t bl1 = *(uint32_t*)&Bs_lo[nb*LDA + k0 + 8 + 2*tg];
                    #pragma unroll
                    for (int mf = 0; mf < MF; mf++) {
                        mma_bf16(c[mf][nf], al[mf], bh0, bh1);
                        mma_bf16(c[mf][nf], ah[mf], bl0, bl1);
                    }
                }
            }
        }
        __syncthreads();
    }
    #pragma unroll
    for (int mf = 0; mf < MF; mf++) {
        int r0 = m0 + wm*MF*16 + mf*16 + g;
        #pragma unroll
        for (int nf = 0; nf < NF; nf++) {
            int cb = n0 + wn*NF*8 + nf*8 + 2*tg;
            C[(size_t)r0*N + cb]       = c[mf][nf][0] + bias[cb];
            C[(size_t)r0*N + cb + 1]   = c[mf][nf][1] + bias[cb+1];
            C[(size_t)(r0+8)*N + cb]   = c[mf][nf][2] + bias[cb];
            C[(size_t)(r0+8)*N + cb+1] = c[mf][nf][3] + bias[cb+1];
        }
    }
}

// ---------------- k_hid_mma: per-batch 128x128x64, 1-pass bf16, fused epilogue + copy ----
__global__ __launch_bounds__(256) void k_hid_mma(const float* __restrict__ hmem,
                                                 float* __restrict__ out_hmem) {
    constexpr int LDA = 72;
    __shared__ __align__(16) bf16 As_hi[128*LDA];
    __shared__ __align__(16) bf16 Bs_hi[128*LDA];
    __shared__ float s_base[128], s_veca[128], s_head[128];
    int tid = threadIdx.x;
    int w = tid >> 5, lane = tid & 31, g = lane >> 2, tg = lane & 3;
    int wm = w >> 2, wn = w & 3;
    int b = blockIdx.x;

    const float4* src = (const float4*)(hmem + (size_t)b*8192);
    float4*       dst = (float4*)(out_hmem + (size_t)b*8192);
    for (int i = tid; i < 2048; i += 256) {
        float4 v = src[i];
        dst[i] = v;
        int row = i >> 4, c4 = (i & 15) * 4;
        uint2 hh; hh.x = pack_hi2(v.x, v.y); hh.y = pack_hi2(v.z, v.w);
        *(uint2*)&As_hi[row*LDA + c4] = hh;
    }
    for (int i = tid; i < 1024; i += 256) {
        int r = i >> 3, q = i & 7;
        *(uint4*)&Bs_hi[r*LDA + q*8] = *(const uint4*)&g_Wm_hi[r*64 + q*8];
    }
    if (tid < 128) {
        s_base[tid] = g_base[(size_t)b*128 + tid];
        s_veca[tid] = g_veca[tid];
        s_head[tid] = 0.f;
    }
    __syncthreads();

    uint32_t a_lane_off = (uint32_t)(((((lane>>3)&1)*8 + (lane&7))*LDA + (lane>>4)*8) * 2);
    uint32_t as_base = (uint32_t)__cvta_generic_to_shared(As_hi) + (uint32_t)(wm*64*LDA*2) + a_lane_off;

    float c[4][4][4] = {};
    #pragma unroll
    for (int k0 = 0; k0 < 64; k0 += 16) {
        uint32_t ah[4][4];
        #pragma unroll
        for (int mf = 0; mf < 4; mf++)
            LDSM_X4(ah[mf], as_base + (uint32_t)((mf*16*LDA + k0)*2));
        #pragma unroll
        for (int nf = 0; nf < 4; nf++) {
            int nb = wn*32 + nf*8 + g;
            uint32_t bh0 = *(uint32_t*)&Bs_hi[nb*LDA + k0 + 2*tg];
            uint32_t bh1 = *(uint32_t*)&Bs_hi[nb*LDA + k0 + 8 + 2*tg];
            #pragma unroll
            for (int mf = 0; mf < 4; mf++) mma_bf16(c[mf][nf], ah[mf], bh0, bh1);
        }
    }

    // head[m] += tanh(c + base[k'] + keyW[m][k']) * veca[k']
    #pragma unroll
    for (int mf = 0; mf < 4; mf++) {
        int r0 = wm*64 + mf*16 + g, r1 = r0 + 8;
        float hs0 = 0.f, hs1 = 0.f;
        #pragma unroll
        for (int nf = 0; nf < 4; nf++) {
            int cb = wn*32 + nf*8 + 2*tg;
            float v;
            v = c[mf][nf][0] + s_base[cb]   + g_keyW[r0*128 + cb];   hs0 += tanh_fast(v)*s_veca[cb];
            v = c[mf][nf][1] + s_base[cb+1] + g_keyW[r0*128 + cb+1]; hs0 += tanh_fast(v)*s_veca[cb+1];
            v = c[mf][nf][2] + s_base[cb]   + g_keyW[r1*128 + cb];   hs1 += tanh_fast(v)*s_veca[cb];
            v = c[mf][nf][3] + s_base[cb+1] + g_keyW[r1*128 + cb+1]; hs1 += tanh_fast(v)*s_veca[cb+1];
        }
        atomicAdd(&s_head[r0], hs0);
        atomicAdd(&s_head[r1], hs1);
    }
    __syncthreads();
    if (tid < 128) g_head[(size_t)b*128 + tid] = s_head[tid];
}

// ------- k_head_r_ab: l2n + gumbel argmax + r gather + alpha/beta (fused) -------
__global__ __launch_bounds__(128) void k_head_r_ab(
    const float* __restrict__ prev, const float* __restrict__ nsm,
    const float* __restrict__ hmem, const float* __restrict__ x,
    const float* __restrict__ h, const float* __restrict__ W1,
    const float* __restrict__ b1, const float* __restrict__ nsig,
    float* __restrict__ d_out) {
    __shared__ float red[128];
    __shared__ float sv[128];
    __shared__ int   si[128];
    __shared__ float sh_r[64];
    __shared__ float red1[128];
    int b = blockIdx.x, t = threadIdx.x;
    float val = g_head[(size_t)b*128 + t] - 100.f * prev[b*128 + t];
    red[t] = val * val;
    __syncthreads();
    for (int s = 64; s > 0; s >>= 1) { if (t < s) red[t] += red[t+s]; __syncthreads(); }
    float norm = fmaxf(sqrtf(red[0]), 1e-12f);
    float z = val / norm + gumbel(nsm[b*128 + t]);
    sv[t] = z; si[t] = t;
    __syncthreads();
    for (int s = 64; s > 0; s >>= 1) {
        if (t < s && sv[t+s] > sv[t]) { sv[t] = sv[t+s]; si[t] = si[t+s]; }
        __syncthreads();
    }
    int best = si[0];
    if (t == 0) g_idx[b] = best;
    if (t < 64) {
        float rv = hmem[((size_t)b*128 + best)*64 + t];
        g_r[b*64 + t] = rv;
        sh_r[t] = rv;
        d_out[(size_t)b*OC + 512 + t] = rv;
    }
    __syncthreads();
    // alpha/beta: dot(concat0, W1[:,0:2])
    float s0 = 0.f, s1 = 0.f;
    for (int k = t; k < CAT0; k += 128) {
        float a = (k < 256) ? x[b*256+k] : (k < 768) ? h[b*512 + (k-256)] : sh_r[k-768];
        s0 += a * W1[k*2];
        s1 += a * W1[k*2 + 1];
    }
    red[t] = s0; red1[t] = s1;
    __syncthreads();
    for (int s = 64; s > 0; s >>= 1) {
        if (t < s) { red[t] += red[t+s]; red1[t] += red1[t+s]; }
        __syncthreads();
    }
    if (t == 0) {
        const float ST = (float)(10.0/3.0);
        g_ab[b*2]     = sigm((red[0]  + b1[0] + gumbel(nsig[b*2]))   * ST);
        g_ab[b*2 + 1] = sigm((red1[0] + b1[1] + gumbel(nsig[b*2+1])) * ST);
    }
}

// ---------------- k_ep: LSTM epilogue -> new_h into output[:, :512] ----------------
__global__ void k_ep(const float* __restrict__ c, float* __restrict__ d_out) {
    int gid = blockIdx.x * blockDim.x + threadIdx.x;
    int b = gid >> 9, j = gid & 511;
    float i_ = g_G[(size_t)b*GN + j];
    float f_ = g_G[(size_t)b*GN + 512 + j];
    float o_ = g_G[(size_t)b*GN + 1024 + j];
    float p  = g_P[(size_t)b*HS + j];
    float nc = c[gid] * sigm(f_ + 1.f) + sigm(i_) * tanhf(p);
    float nh = tanhf(nc) * sigm(o_);
    d_out[(size_t)b*OC + j] = nh;
}

// ---------------- k_whw: write replaced hmem row ----------------
__global__ void k_whw(const int* __restrict__ memcnt, float* __restrict__ out_hmem) {
    int b = blockIdx.x, t = threadIdx.x;
    int mc = memcnt[0];
    int row = (mc < MS) ? mc : g_idx[b];
    out_hmem[((size_t)b*MS + row)*RS + t] = g_hw[(size_t)b*RS + t];
}

// ---------------- launch ----------------
extern "C" void kernel_launch(void* const* d_in, const int* in_sizes, int n_in,
                              void* d_out, int out_size) {
    const float* x        = (const float*)d_in[0];
    const float* h        = (const float*)d_in[1];
    const float* c        = (const float*)d_in[2];
    const float* hmem     = (const float*)d_in[3];
    const float* u_t      = (const float*)d_in[4];
    const float* prev     = (const float*)d_in[5];
    const float* W_full   = (const float*)d_in[6];
    const float* bias     = (const float*)d_in[7];
    const float* W_full1  = (const float*)d_in[8];
    const float* bias1    = (const float*)d_in[9];
    const float* W_full2  = (const float*)d_in[10];
    const float* bias2    = (const float*)d_in[11];
    const float* keys     = (const float*)d_in[12];
    const float* vec_a    = (const float*)d_in[13];
    const float* W_fc     = (const float*)d_in[14];
    const float* b_fc     = (const float*)d_in[15];
    const float* W_fc1    = (const float*)d_in[16];
    const float* b_fc1    = (const float*)d_in[17];
    const float* noise_sm = (const float*)d_in[18];
    const float* noise_sig= (const float*)d_in[19];
    const int*   memcnt   = (const int*)d_in[20];

    float* out      = (float*)d_out;
    float* out_hmem = out + (size_t)BSZ * OC;

    float *pG, *pP, *pab, *pbase, *phw, *pr, *puinv;
    bf16 *pWGh, *pWGl, *pWPh, *pWPl, *pWbh, *pWwh, *pWwl;
    cudaGetSymbolAddress((void**)&pG,    g_G);
    cudaGetSymbolAddress((void**)&pP,    g_P);
    cudaGetSymbolAddress((void**)&pab,   g_ab);
    cudaGetSymbolAddress((void**)&pbase, g_base);
    cudaGetSymbolAddress((void**)&phw,   g_hw);
    cudaGetSymbolAddress((void**)&pr,    g_r);
    cudaGetSymbolAddress((void**)&puinv, g_uinv);
    cudaGetSymbolAddress((void**)&pWGh,  g_WG_hi);
    cudaGetSymbolAddress((void**)&pWGl,  g_WG_lo);
    cudaGetSymbolAddress((void**)&pWPh,  g_WP_hi);
    cudaGetSymbolAddress((void**)&pWPl,  g_WP_lo);
    cudaGetSymbolAddress((void**)&pWbh,  g_Wb_hi);
    cudaGetSymbolAddress((void**)&pWwh,  g_Ww_hi);
    cudaGetSymbolAddress((void**)&pWwl,  g_Ww_lo);

    // 1. all prep
    k_prep<<<T_ALL, 256>>>(W_full, W_full2, W_fc, W_fc1, keys, vec_a, u_t);
    // 2. base = [x,c,u^]@Wb + b_fc   (2048 x 128 x 896), 1-pass bf16
    mgemm<2,4,2,4, 2,0,1><<<dim3(1, BSZ/64), 256>>>(
        x, c, u_t, puinv, pWbh, pWbh, pbase, b_fc, 128, XCU);
    // 3. hid + head (1-pass bf16) + hmem copy
    k_hid_mma<<<BSZ, 256>>>(hmem, out_hmem);
    // 4. argmax read + r gather + alpha/beta
    k_head_r_ab<<<BSZ, 128>>>(prev, noise_sm, hmem, x, h, W_full1, bias1, noise_sig, out);
    // 5. G = [x,h,r]@W_full + bias   (2048 x 1536 x 832), 3-pass
    mgemm<2,4,4,4, 1,0,3><<<dim3(GN/128, BSZ/128), 256>>>(
        x, h, pr, pab, pWGh, pWGl, pG, bias, GN, CAT0);
    // 6. P = ([x,h,r]*scale)@W_full2 + bias2   (2048 x 512 x 832), 3-pass
    mgemm<2,4,4,4, 1,1,3><<<dim3(HS/128, BSZ/128), 256>>>(
        x, h, pr, pab, pWPh, pWPl, pP, bias2, HS, CAT0);
    // 7. LSTM epilogue -> new_h
    k_ep<<<(BSZ*HS)/256, 256>>>(c, out);
    // 8. h_w = [x,new_h]@W_fc1 + b_fc1   (2048 x 64 x 768), 3-pass
    mgemm<4,2,1,4, 3,0,3><<<dim3(1, BSZ/64), 256>>>(
        x, out, nullptr, nullptr, pWwh, pWwl, phw, b_fc1, 64, 768);
    // 9. hmem row replace
    k_whw<<<BSZ, 64>>>(memcnt, out_hmem);
    (void)in_sizes; (void)n_in; (void)out_size;
}

// round 5
// speedup vs baseline: 2.3788x; 1.1771x over previous
#include <cuda_runtime.h>
#include <cuda_bf16.h>
#include <math.h>
#include <stdint.h>

#define BSZ 2048
#define HS  512
#define RS  64
#define MS  128
#define CAT0 832
#define XCU 896
#define GN  1536
#define OC  576

typedef __nv_bfloat16 bf16;

// ---------------- scratch (device globals; no allocations) ----------------
__device__ __align__(16) float g_base [BSZ*128];
__device__ __align__(16) float g_keyW [128*128];   // [m][k']
__device__ __align__(16) float g_ab   [BSZ*2];
__device__             int   g_idx  [BSZ];
__device__ __align__(16) float g_r    [BSZ*RS];
__device__ __align__(16) float g_G    [BSZ*GN];
__device__ __align__(16) float g_P    [BSZ*HS];
__device__ __align__(16) float g_veca [128];
__device__ __align__(16) float g_uinv [BSZ];
// bf16 split weights, TRANSPOSED [N][K]
__device__ __align__(16) bf16 g_WG_hi[GN*CAT0],  g_WG_lo[GN*CAT0];
__device__ __align__(16) bf16 g_WP_hi[HS*CAT0],  g_WP_lo[HS*CAT0];
__device__ __align__(16) bf16 g_Wb_hi[128*XCU];
__device__ __align__(16) bf16 g_Ww_hi[64*768],   g_Ww_lo[64*768];
__device__ __align__(16) bf16 g_Wm_hi[128*64];

__device__ __forceinline__ float tanh_fast(float x) {
    float y; asm("tanh.approx.f32 %0, %1;" : "=f"(y) : "f"(x)); return y;
}
__device__ __forceinline__ float sigm(float x) { return 1.f/(1.f+expf(-x)); }
__device__ __forceinline__ float gumbel(float u) {
    return -logf(1e-20f - logf(1e-20f + u));
}
__device__ __forceinline__ void split2(float a, float b, uint32_t& hi, uint32_t& lo) {
    __nv_bfloat162 h, l;
    h.x = __float2bfloat16(a); h.y = __float2bfloat16(b);
    l.x = __float2bfloat16(a - __bfloat162float(h.x));
    l.y = __float2bfloat16(b - __bfloat162float(h.y));
    hi = *(uint32_t*)&h; lo = *(uint32_t*)&l;
}
__device__ __forceinline__ uint32_t pack_hi2(float a, float b) {
    __nv_bfloat162 h; h.x = __float2bfloat16(a); h.y = __float2bfloat16(b);
    return *(uint32_t*)&h;
}
__device__ __forceinline__ void mma_bf16(float* c, const uint32_t* a, uint32_t b0, uint32_t b1) {
    asm volatile("mma.sync.aligned.m16n8k16.row.col.f32.bf16.bf16.f32 "
        "{%0,%1,%2,%3},{%4,%5,%6,%7},{%8,%9},{%0,%1,%2,%3};"
        : "+f"(c[0]), "+f"(c[1]), "+f"(c[2]), "+f"(c[3])
        : "r"(a[0]), "r"(a[1]), "r"(a[2]), "r"(a[3]), "r"(b0), "r"(b1));
}
#define LDSM_X4(r, addr) \
    asm volatile("ldmatrix.sync.aligned.m8n8.x4.shared.b16 {%0,%1,%2,%3}, [%4];" \
        : "=r"((r)[0]), "=r"((r)[1]), "=r"((r)[2]), "=r"((r)[3]) : "r"(addr))
#define CP_ASYNC16(saddr, gptr) \
    asm volatile("cp.async.cg.shared.global [%0], [%1], 16;" :: "r"(saddr), "l"(gptr))
#define CP_COMMIT() asm volatile("cp.async.commit_group;" ::: "memory")
#define CP_WAIT0()  asm volatile("cp.async.wait_group 0;" ::: "memory")
__device__ __forceinline__ uint32_t sptr(const void* p) {
    return (uint32_t)__cvta_generic_to_shared(p);
}

// ---------------- k_prep: weight splits + keyW + uinv + veca ----------------
__device__ void tsplit_tile(const float* __restrict__ src, bf16* __restrict__ dhi,
                            bf16* __restrict__ dlo, int K, int N, int split, int extra,
                            int tile, int tid) {
    __shared__ float t[32][33];
    int nt = N/32;
    int n0 = (tile % nt)*32, k0 = (tile / nt)*32;
    int tx = tid & 31, ty = tid >> 5;
    for (int r = ty; r < 32; r += 8) {
        int k = k0 + r; int sr = (k < split) ? k : k + extra;
        t[r][tx] = src[(size_t)sr*N + n0 + tx];
    }
    __syncthreads();
    for (int r = ty; r < 32; r += 8) {
        float v = t[tx][r];
        bf16 hi = __float2bfloat16(v);
        size_t o = (size_t)(n0 + r)*K + k0 + tx;
        dhi[o] = hi;
        if (dlo) dlo[o] = __float2bfloat16(v - __bfloat162float(hi));
    }
}

#define T_WG 1248
#define T_WP (T_WG + 416)
#define T_WB (T_WP + 112)
#define T_WW (T_WB + 48)
#define T_WM (T_WW + 8)
#define T_KW (T_WM + 64)
#define T_UN (T_KW + 256)
#define T_ALL (T_UN + 1)

__global__ __launch_bounds__(256) void k_prep(
    const float* __restrict__ W_full, const float* __restrict__ W_full2,
    const float* __restrict__ W_fc,   const float* __restrict__ W_fc1,
    const float* __restrict__ keys,   const float* __restrict__ vec_a,
    const float* __restrict__ u) {
    int blk = blockIdx.x, tid = threadIdx.x;
    if (blk < T_WG) {
        tsplit_tile(W_full, g_WG_hi, g_WG_lo, CAT0, GN, CAT0, 0, blk, tid);
    } else if (blk < T_WP) {
        tsplit_tile(W_full2, g_WP_hi, g_WP_lo, CAT0, HS, CAT0, 0, blk - T_WG, tid);
    } else if (blk < T_WB) {
        tsplit_tile(W_fc, g_Wb_hi, nullptr, XCU, 128, 768, 128, blk - T_WP, tid);
    } else if (blk < T_WW) {
        tsplit_tile(W_fc1, g_Ww_hi, g_Ww_lo, 768, 64, 768, 0, blk - T_WB, tid);
    } else if (blk < T_WM) {
        tsplit_tile(W_fc + 832*128, g_Wm_hi, nullptr, 64, 128, 64, 0, blk - T_WW, tid);
    } else if (blk < T_KW) {
        __shared__ float krow[2][64];
        int sub = tid >> 7, t = tid & 127;
        int m = (blk - T_WM)*2 + sub;
        if (t < 64) krow[sub][t] = keys[m*64 + t];
        __syncthreads();
        float acc = 0.f;
        #pragma unroll 8
        for (int r = 0; r < 64; r++) acc += krow[sub][r] * W_fc[(768+r)*128 + t];
        g_keyW[m*128 + t] = acc;
    } else if (blk < T_UN) {
        int w = tid >> 5, lane = tid & 31;
        int b = (blk - T_KW)*8 + w;
        float s = 0.f;
        #pragma unroll
        for (int j = lane; j < 128; j += 32) { float v = u[b*128+j]; s += v*v; }
        #pragma unroll
        for (int o = 16; o > 0; o >>= 1) s += __shfl_down_sync(0xffffffffu, s, o);
        if (lane == 0) g_uinv[b] = 1.f / fmaxf(sqrtf(s), 1e-12f);
    } else {
        if (tid < 128) g_veca[tid] = vec_a[tid];
    }
}

// ---------------- pipelined warp-MMA GEMM with fused A gather ----------------
// SRC: 1=[x,h,r] (CAT0), 2=[x,c,u*uinv] (XCU), 3=[x,new_h from d_out] (768)
// SCALE: alpha/beta per-segment scaling (SRC 1); OUTM: 1 = scatter rows to out_hmem
template<int WM, int WN, int MF, int NF, int SRC, int SCALE, int PASSES, int OUTM>
__global__ __launch_bounds__(WM*WN*32) void mgemm(
    const float* __restrict__ p0, const float* __restrict__ p1,
    const float* __restrict__ p2, const float* __restrict__ aux,
    const bf16* __restrict__ BT_hi, const bf16* __restrict__ BT_lo,
    float* __restrict__ C, const float* __restrict__ bias,
    const int* __restrict__ memcnt, int N, int K) {
    constexpr int BK = 32, LDA = 40;
    constexpr int BM = WM*MF*16, BN = WN*NF*8, NT = WM*WN*32;
    constexpr int NBUF = (PASSES > 1) ? 2 : 1;
    constexpr int ASZ = BM*LDA, BSZE = BN*LDA;
    constexpr int STAGE = (ASZ + BSZE) * NBUF;
    constexpr int ALOADS = BM*BK/4/NT;
    constexpr int BCHUNK = BN*BK/8/NT;
    extern __shared__ __align__(16) bf16 sm[];
    int tid = threadIdx.x;
    int w = tid >> 5, lane = tid & 31, g = lane >> 2, tg = lane & 3;
    int wm = w / WN, wn = w % WN;
    int m0 = blockIdx.y*BM, n0 = blockIdx.x*BN;
    const int KT = K / BK;
    float c[MF][NF][4] = {};

    uint32_t a_off = (uint32_t)(((((lane>>3)&1)*8 + (lane&7))*LDA + (lane>>4)*8) * 2);
    uint32_t b_off = (uint32_t)((((lane&7) + ((lane>>4)&1)*8)*LDA + ((lane>>3)&1)*8) * 2);

    float4 av[ALOADS];
    auto ldA = [&](int kt) {
        #pragma unroll
        for (int l = 0; l < ALOADS; l++) {
            int i = tid + l*NT;
            int row = i/(BK/4), q = i%(BK/4);
            int gr = m0 + row, kk = kt*BK + q*4;
            float4 v;
            if (SRC == 1) {
                if (kk < 256)      v = *(const float4*)&p0[(size_t)gr*256 + kk];
                else if (kk < 768) v = *(const float4*)&p1[(size_t)gr*512 + kk-256];
                else               v = *(const float4*)&p2[(size_t)gr*64  + kk-768];
                if (SCALE) {
                    float s = (kk >= 768) ? aux[gr*2+1] : (kk >= 256) ? aux[gr*2] : 1.f;
                    v.x *= s; v.y *= s; v.z *= s; v.w *= s;
                }
            } else if (SRC == 2) {
                if (kk < 256)      v = *(const float4*)&p0[(size_t)gr*256 + kk];
                else if (kk < 768) v = *(const float4*)&p1[(size_t)gr*512 + kk-256];
                else {
                    v = *(const float4*)&p2[(size_t)gr*128 + kk-768];
                    float s = aux[gr];
                    v.x *= s; v.y *= s; v.z *= s; v.w *= s;
                }
            } else {
                if (kk < 256)      v = *(const float4*)&p0[(size_t)gr*256 + kk];
                else               v = *(const float4*)&p1[(size_t)gr*OC + kk-256];
            }
            av[l] = v;
        }
    };
    auto stA = [&](int s) {
        bf16* Ah = sm + s*STAGE;
        bf16* Al = Ah + ASZ;
        #pragma unroll
        for (int l = 0; l < ALOADS; l++) {
            int i = tid + l*NT;
            int row = i/(BK/4), q = i%(BK/4);
            float4 v = av[l];
            if (PASSES > 1) {
                uint32_t h0, l0, h1, l1;
                split2(v.x, v.y, h0, l0);
                split2(v.z, v.w, h1, l1);
                uint2 hh; hh.x = h0; hh.y = h1;
                uint2 ll; ll.x = l0; ll.y = l1;
                *(uint2*)&Ah[row*LDA + q*4] = hh;
                *(uint2*)&Al[row*LDA + q*4] = ll;
            } else {
                uint2 hh; hh.x = pack_hi2(v.x, v.y); hh.y = pack_hi2(v.z, v.w);
                *(uint2*)&Ah[row*LDA + q*4] = hh;
            }
        }
    };
    auto ldB = [&](int s, int kt) {
        bf16* Bh = sm + s*STAGE + ASZ*NBUF;
        bf16* Bl = Bh + BSZE;
        #pragma unroll
        for (int l = 0; l < BCHUNK; l++) {
            int i = tid + l*NT;
            int r = i/(BK/8), q = i%(BK/8);
            CP_ASYNC16(sptr(&Bh[r*LDA + q*8]), &BT_hi[(size_t)(n0+r)*K + kt*BK + q*8]);
            if (PASSES > 1)
                CP_ASYNC16(sptr(&Bl[r*LDA + q*8]), &BT_lo[(size_t)(n0+r)*K + kt*BK + q*8]);
        }
    };

    // prologue
    ldA(0); ldB(0, 0); CP_COMMIT(); stA(0);
    CP_WAIT0(); __syncthreads();

    for (int kt = 0; kt < KT; kt++) {
        int s = kt & 1;
        bool nxt = (kt + 1 < KT);
        if (nxt) { ldB(s^1, kt+1); CP_COMMIT(); ldA(kt+1); }

        uint32_t ahb = sptr(sm + s*STAGE) + (uint32_t)(wm*MF*16*LDA*2) + a_off;
        uint32_t alb = ahb + (uint32_t)(ASZ*2);
        uint32_t bhb = sptr(sm + s*STAGE + ASZ*NBUF) + (uint32_t)(wn*NF*8*LDA*2) + b_off;
        uint32_t blb = bhb + (uint32_t)(BSZE*2);
        #pragma unroll
        for (int k0 = 0; k0 < BK; k0 += 16) {
            uint32_t ah[MF][4], al[MF][4];
            #pragma unroll
            for (int mf = 0; mf < MF; mf++) {
                LDSM_X4(ah[mf], ahb + (uint32_t)((mf*16*LDA + k0)*2));
                if (PASSES > 1)
                    LDSM_X4(al[mf], alb + (uint32_t)((mf*16*LDA + k0)*2));
            }
            #pragma unroll
            for (int np = 0; np < NF/2; np++) {
                uint32_t bh[4];
                LDSM_X4(bh, bhb + (uint32_t)((np*16*LDA + k0)*2));
                #pragma unroll
                for (int mf = 0; mf < MF; mf++) {
                    mma_bf16(c[mf][2*np],   ah[mf], bh[0], bh[1]);
                    mma_bf16(c[mf][2*np+1], ah[mf], bh[2], bh[3]);
                }
                if (PASSES > 1) {
                    uint32_t bl[4];
                    LDSM_X4(bl, blb + (uint32_t)((np*16*LDA + k0)*2));
                    #pragma unroll
                    for (int mf = 0; mf < MF; mf++) {
                        mma_bf16(c[mf][2*np],   al[mf], bh[0], bh[1]);
                        mma_bf16(c[mf][2*np+1], al[mf], bh[2], bh[3]);
                        mma_bf16(c[mf][2*np],   ah[mf], bl[0], bl[1]);
                        mma_bf16(c[mf][2*np+1], ah[mf], bl[2], bl[3]);
                    }
                }
            }
        }
        if (nxt) stA(s^1);
        CP_WAIT0(); __syncthreads();
    }

    int mc = OUTM ? memcnt[0] : 0;
    #pragma unroll
    for (int mf = 0; mf < MF; mf++) {
        int r0 = m0 + wm*MF*16 + mf*16 + g;
        #pragma unroll
        for (int nf = 0; nf < NF; nf++) {
            int cb = n0 + wn*NF*8 + nf*8 + 2*tg;
            float v0 = c[mf][nf][0] + bias[cb];
            float v1 = c[mf][nf][1] + bias[cb+1];
            float v2 = c[mf][nf][2] + bias[cb];
            float v3 = c[mf][nf][3] + bias[cb+1];
            if (OUTM) {
                int row0 = (mc < MS) ? mc : g_idx[r0];
                int row1 = (mc < MS) ? mc : g_idx[r0+8];
                float* d0 = &C[((size_t)r0*MS + row0)*RS];
                float* d1 = &C[((size_t)(r0+8)*MS + row1)*RS];
                d0[cb] = v0; d0[cb+1] = v1;
                d1[cb] = v2; d1[cb+1] = v3;
            } else {
                C[(size_t)r0*N + cb]       = v0;
                C[(size_t)r0*N + cb + 1]   = v1;
                C[(size_t)(r0+8)*N + cb]   = v2;
                C[(size_t)(r0+8)*N + cb+1] = v3;
            }
        }
    }
}

// ---------------- k_hid_mma: 128x128x64 MMA + head + argmax + r + ab (all fused) ----
__global__ __launch_bounds__(256) void k_hid_mma(
    const float* __restrict__ hmem, float* __restrict__ out_hmem,
    const float* __restrict__ prev, const float* __restrict__ nsm,
    const float* __restrict__ x, const float* __restrict__ h,
    const float* __restrict__ W1, const float* __restrict__ b1,
    const float* __restrict__ nsig, float* __restrict__ d_out) {
    constexpr int LDA = 72;
    __shared__ __align__(16) bf16 As_hi[128*LDA];
    __shared__ __align__(16) bf16 Bs_hi[128*LDA];
    __shared__ float s_base[128], s_veca[128], s_head[128];
    __shared__ float red[256], red1[256];
    __shared__ float sv[128];
    __shared__ int   si[128];
    __shared__ float sh_r[64];
    int tid = threadIdx.x;
    int w = tid >> 5, lane = tid & 31, g = lane >> 2, tg = lane & 3;
    int wm = w >> 2, wn = w & 3;
    int b = blockIdx.x;

    const float4* src = (const float4*)(hmem + (size_t)b*8192);
    float4*       dst = (float4*)(out_hmem + (size_t)b*8192);
    for (int i = tid; i < 2048; i += 256) {
        float4 v = src[i];
        dst[i] = v;
        int row = i >> 4, c4 = (i & 15) * 4;
        uint2 hh; hh.x = pack_hi2(v.x, v.y); hh.y = pack_hi2(v.z, v.w);
        *(uint2*)&As_hi[row*LDA + c4] = hh;
    }
    for (int i = tid; i < 1024; i += 256) {
        int r = i >> 3, q = i & 7;
        *(uint4*)&Bs_hi[r*LDA + q*8] = *(const uint4*)&g_Wm_hi[r*64 + q*8];
    }
    if (tid < 128) {
        s_base[tid] = g_base[(size_t)b*128 + tid];
        s_veca[tid] = g_veca[tid];
        s_head[tid] = 0.f;
    }
    __syncthreads();

    uint32_t a_lane_off = (uint32_t)(((((lane>>3)&1)*8 + (lane&7))*LDA + (lane>>4)*8) * 2);
    uint32_t as_base = sptr(As_hi) + (uint32_t)(wm*64*LDA*2) + a_lane_off;

    float c[4][4][4] = {};
    #pragma unroll
    for (int k0 = 0; k0 < 64; k0 += 16) {
        uint32_t ah[4][4];
        #pragma unroll
        for (int mf = 0; mf < 4; mf++)
            LDSM_X4(ah[mf], as_base + (uint32_t)((mf*16*LDA + k0)*2));
        #pragma unroll
        for (int nf = 0; nf < 4; nf++) {
            int nb = wn*32 + nf*8 + g;
            uint32_t bh0 = *(uint32_t*)&Bs_hi[nb*LDA + k0 + 2*tg];
            uint32_t bh1 = *(uint32_t*)&Bs_hi[nb*LDA + k0 + 8 + 2*tg];
            #pragma unroll
            for (int mf = 0; mf < 4; mf++) mma_bf16(c[mf][nf], ah[mf], bh0, bh1);
        }
    }

    #pragma unroll
    for (int mf = 0; mf < 4; mf++) {
        int r0 = wm*64 + mf*16 + g, r1 = r0 + 8;
        float hs0 = 0.f, hs1 = 0.f;
        #pragma unroll
        for (int nf = 0; nf < 4; nf++) {
            int cb = wn*32 + nf*8 + 2*tg;
            float v;
            v = c[mf][nf][0] + s_base[cb]   + g_keyW[r0*128 + cb];   hs0 += tanh_fast(v)*s_veca[cb];
            v = c[mf][nf][1] + s_base[cb+1] + g_keyW[r0*128 + cb+1]; hs0 += tanh_fast(v)*s_veca[cb+1];
            v = c[mf][nf][2] + s_base[cb]   + g_keyW[r1*128 + cb];   hs1 += tanh_fast(v)*s_veca[cb];
            v = c[mf][nf][3] + s_base[cb+1] + g_keyW[r1*128 + cb+1]; hs1 += tanh_fast(v)*s_veca[cb+1];
        }
        atomicAdd(&s_head[r0], hs0);
        atomicAdd(&s_head[r1], hs1);
    }
    __syncthreads();

    // --- fused tail: l2n(head - 100*prev) + gumbel argmax -> r gather -> alpha/beta ---
    int t = tid;
    float val = 0.f;
    if (t < 128) {
        val = s_head[t] - 100.f * prev[b*128 + t];
        red[t] = val * val;
    }
    __syncthreads();
    if (t < 64) red[t] += red[t+64];
    __syncthreads();
    for (int s = 32; s > 0; s >>= 1) { if (t < s) red[t] += red[t+s]; __syncthreads(); }
    if (t < 128) {
        float norm = fmaxf(sqrtf(red[0]), 1e-12f);
        sv[t] = val / norm + gumbel(nsm[b*128 + t]);
        si[t] = t;
    }
    __syncthreads();
    for (int s = 64; s > 0; s >>= 1) {
        if (t < s && sv[t+s] > sv[t]) { sv[t] = sv[t+s]; si[t] = si[t+s]; }
        __syncthreads();
    }
    int best = si[0];
    if (t == 0) g_idx[b] = best;
    if (t < 64) {
        float rv = hmem[((size_t)b*128 + best)*64 + t];
        g_r[b*64 + t] = rv;
        sh_r[t] = rv;
        d_out[(size_t)b*OC + 512 + t] = rv;
    }
    __syncthreads();
    float s0 = 0.f, s1 = 0.f;
    for (int k = t; k < CAT0; k += 256) {
        float a = (k < 256) ? x[b*256+k] : (k < 768) ? h[b*512 + (k-256)] : sh_r[k-768];
        s0 += a * W1[k*2];
        s1 += a * W1[k*2 + 1];
    }
    red[t] = s0; red1[t] = s1;
    __syncthreads();
    for (int s = 128; s > 0; s >>= 1) {
        if (t < s) { red[t] += red[t+s]; red1[t] += red1[t+s]; }
        __syncthreads();
    }
    if (t == 0) {
        const float ST = (float)(10.0/3.0);
        g_ab[b*2]     = sigm((red[0]  + b1[0] + gumbel(nsig[b*2]))   * ST);
        g_ab[b*2 + 1] = sigm((red1[0] + b1[1] + gumbel(nsig[b*2+1])) * ST);
    }
}

// ---------------- k_ep: LSTM epilogue -> new_h into output[:, :512] ----------------
__global__ void k_ep(const float* __restrict__ c, float* __restrict__ d_out) {
    int gid = blockIdx.x * blockDim.x + threadIdx.x;
    int b = gid >> 9, j = gid & 511;
    float i_ = g_G[(size_t)b*GN + j];
    float f_ = g_G[(size_t)b*GN + 512 + j];
    float o_ = g_G[(size_t)b*GN + 1024 + j];
    float p  = g_P[(size_t)b*HS + j];
    float nc = c[gid] * sigm(f_ + 1.f) + sigm(i_) * tanhf(p);
    float nh = tanhf(nc) * sigm(o_);
    d_out[(size_t)b*OC + j] = nh;
}

// ---------------- launch ----------------
extern "C" void kernel_launch(void* const* d_in, const int* in_sizes, int n_in,
                              void* d_out, int out_size) {
    const float* x        = (const float*)d_in[0];
    const float* h        = (const float*)d_in[1];
    const float* c        = (const float*)d_in[2];
    const float* hmem     = (const float*)d_in[3];
    const float* u_t      = (const float*)d_in[4];
    const float* prev     = (const float*)d_in[5];
    const float* W_full   = (const float*)d_in[6];
    const float* bias     = (const float*)d_in[7];
    const float* W_full1  = (const float*)d_in[8];
    const float* bias1    = (const float*)d_in[9];
    const float* W_full2  = (const float*)d_in[10];
    const float* bias2    = (const float*)d_in[11];
    const float* keys     = (const float*)d_in[12];
    const float* vec_a    = (const float*)d_in[13];
    const float* W_fc     = (const float*)d_in[14];
    const float* b_fc     = (const float*)d_in[15];
    const float* W_fc1    = (const float*)d_in[16];
    const float* b_fc1    = (const float*)d_in[17];
    const float* noise_sm = (const float*)d_in[18];
    const float* noise_sig= (const float*)d_in[19];
    const int*   memcnt   = (const int*)d_in[20];

    float* out      = (float*)d_out;
    float* out_hmem = out + (size_t)BSZ * OC;

    float *pG, *pP, *pab, *pbase, *pr, *puinv;
    bf16 *pWGh, *pWGl, *pWPh, *pWPl, *pWbh, *pWwh, *pWwl;
    cudaGetSymbolAddress((void**)&pG,    g_G);
    cudaGetSymbolAddress((void**)&pP,    g_P);
    cudaGetSymbolAddress((void**)&pab,   g_ab);
    cudaGetSymbolAddress((void**)&pbase, g_base);
    cudaGetSymbolAddress((void**)&pr,    g_r);
    cudaGetSymbolAddress((void**)&puinv, g_uinv);
    cudaGetSymbolAddress((void**)&pWGh,  g_WG_hi);
    cudaGetSymbolAddress((void**)&pWGl,  g_WG_lo);
    cudaGetSymbolAddress((void**)&pWPh,  g_WP_hi);
    cudaGetSymbolAddress((void**)&pWPl,  g_WP_lo);
    cudaGetSymbolAddress((void**)&pWbh,  g_Wb_hi);
    cudaGetSymbolAddress((void**)&pWwh,  g_Ww_hi);
    cudaGetSymbolAddress((void**)&pWwl,  g_Ww_lo);

    // smem bytes: 2 stages * (BM*40 + BN*40)*NBUF*2B
    auto kG    = mgemm<2,4,4,4, 1,0,3, 0>;  // 128x128 tile, 3-pass
    auto kP    = mgemm<2,4,4,2, 1,1,3, 0>;  // 128x64 tile, 3-pass
    auto kBase = mgemm<2,4,1,2, 2,0,1, 0>;  // 32x64 tile, 1-pass
    auto kHw   = mgemm<2,2,1,4, 3,0,3, 1>;  // 32x64 tile, 3-pass, hmem scatter
    cudaFuncSetAttribute((const void*)kG,    cudaFuncAttributeMaxDynamicSharedMemorySize, 81920);
    cudaFuncSetAttribute((const void*)kP,    cudaFuncAttributeMaxDynamicSharedMemorySize, 61440);
    cudaFuncSetAttribute((const void*)kBase, cudaFuncAttributeMaxDynamicSharedMemorySize, 15360);
    cudaFuncSetAttribute((const void*)kHw,   cudaFuncAttributeMaxDynamicSharedMemorySize, 30720);

    // 1. all prep
    k_prep<<<T_ALL, 256>>>(W_full, W_full2, W_fc, W_fc1, keys, vec_a, u_t);
    // 2. base = [x,c,u^]@Wb + b_fc   (2048 x 128 x 896)
    kBase<<<dim3(2, BSZ/32), 256, 15360>>>(
        x, c, u_t, puinv, pWbh, pWbh, pbase, b_fc, nullptr, 128, XCU);
    // 3. hid + head + argmax + r + ab + hmem copy (fully fused)
    k_hid_mma<<<BSZ, 256>>>(hmem, out_hmem, prev, noise_sm, x, h, W_full1, bias1, noise_sig, out);
    // 4. G = [x,h,r]@W_full + bias   (2048 x 1536 x 832)
    kG<<<dim3(GN/128, BSZ/128), 256, 81920>>>(
        x, h, pr, pab, pWGh, pWGl, pG, bias, nullptr, GN, CAT0);
    // 5. P = ([x,h,r]*scale)@W_full2 + bias2   (2048 x 512 x 832)
    kP<<<dim3(HS/64, BSZ/128), 256, 61440>>>(
        x, h, pr, pab, pWPh, pWPl, pP, bias2, nullptr, HS, CAT0);
    // 6. LSTM epilogue -> new_h
    k_ep<<<(BSZ*HS)/256, 256>>>(c, out);
    // 7. h_w = [x,new_h]@W_fc1 + b_fc1 -> scatter into out_hmem rows
    kHw<<<dim3(1, BSZ/32), 128, 30720>>>(
        x, out, nullptr, nullptr, pWwh, pWwl, out_hmem, b_fc1, memcnt, 64, 768);
    (void)in_sizes; (void)n_in; (void)out_size;
}

// round 6
// speedup vs baseline: 2.8103x; 1.1814x over previous
#include <cuda_runtime.h>
#include <cuda_bf16.h>
#include <math.h>
#include <stdint.h>

#define BSZ 2048
#define HS  512
#define RS  64
#define MS  128
#define CAT0 832
#define XCU 896
#define GN  1536
#define OC  576

typedef __nv_bfloat16 bf16;

// ---------------- scratch (device globals; no allocations) ----------------
__device__ __align__(16) float g_base [BSZ*128];
__device__ __align__(16) float g_keyW [128*128];
__device__ __align__(16) float g_ab   [BSZ*2];
__device__             int   g_idx  [BSZ];
__device__ __align__(16) float g_r    [BSZ*RS];
__device__ __align__(16) float g_G    [BSZ*GN];
__device__ __align__(16) float g_P    [BSZ*HS];
__device__ __align__(16) float g_veca [128];
__device__ __align__(16) float g_uinv [BSZ];
__device__ __align__(16) bf16 g_WG_hi[GN*CAT0],  g_WG_lo[GN*CAT0];
__device__ __align__(16) bf16 g_WP_hi[HS*CAT0],  g_WP_lo[HS*CAT0];
__device__ __align__(16) bf16 g_Wb_hi[128*XCU];
__device__ __align__(16) bf16 g_Ww_hi[64*768],   g_Ww_lo[64*768];
__device__ __align__(16) bf16 g_Wm_hi[128*64];

__device__ __forceinline__ float tanh_fast(float x) {
    float y; asm("tanh.approx.f32 %0, %1;" : "=f"(y) : "f"(x)); return y;
}
__device__ __forceinline__ float sigm(float x) { return 1.f/(1.f+expf(-x)); }
__device__ __forceinline__ float gumbel(float u) {
    return -logf(1e-20f - logf(1e-20f + u));
}
__device__ __forceinline__ void split2(float a, float b, uint32_t& hi, uint32_t& lo) {
    __nv_bfloat162 h, l;
    h.x = __float2bfloat16(a); h.y = __float2bfloat16(b);
    l.x = __float2bfloat16(a - __bfloat162float(h.x));
    l.y = __float2bfloat16(b - __bfloat162float(h.y));
    hi = *(uint32_t*)&h; lo = *(uint32_t*)&l;
}
__device__ __forceinline__ uint32_t pack_hi2(float a, float b) {
    __nv_bfloat162 h; h.x = __float2bfloat16(a); h.y = __float2bfloat16(b);
    return *(uint32_t*)&h;
}
__device__ __forceinline__ void mma_bf16(float* c, const uint32_t* a, uint32_t b0, uint32_t b1) {
    asm volatile("mma.sync.aligned.m16n8k16.row.col.f32.bf16.bf16.f32 "
        "{%0,%1,%2,%3},{%4,%5,%6,%7},{%8,%9},{%0,%1,%2,%3};"
        : "+f"(c[0]), "+f"(c[1]), "+f"(c[2]), "+f"(c[3])
        : "r"(a[0]), "r"(a[1]), "r"(a[2]), "r"(a[3]), "r"(b0), "r"(b1));
}
#define LDSM_X4(r, addr) \
    asm volatile("ldmatrix.sync.aligned.m8n8.x4.shared.b16 {%0,%1,%2,%3}, [%4];" \
        : "=r"((r)[0]), "=r"((r)[1]), "=r"((r)[2]), "=r"((r)[3]) : "r"(addr))
#define CP_ASYNC16(saddr, gptr) \
    asm volatile("cp.async.cg.shared.global [%0], [%1], 16;" :: "r"(saddr), "l"(gptr))
#define CP_COMMIT() asm volatile("cp.async.commit_group;" ::: "memory")
#define CP_WAIT0()  asm volatile("cp.async.wait_group 0;" ::: "memory")
__device__ __forceinline__ uint32_t sptr(const void* p) {
    return (uint32_t)__cvta_generic_to_shared(p);
}

// ---------------- k_prep ----------------
__device__ void tsplit_tile(const float* __restrict__ src, bf16* __restrict__ dhi,
                            bf16* __restrict__ dlo, int K, int N, int split, int extra,
                            int tile, int tid) {
    __shared__ float t[32][33];
    int nt = N/32;
    int n0 = (tile % nt)*32, k0 = (tile / nt)*32;
    int tx = tid & 31, ty = tid >> 5;
    for (int r = ty; r < 32; r += 8) {
        int k = k0 + r; int sr = (k < split) ? k : k + extra;
        t[r][tx] = src[(size_t)sr*N + n0 + tx];
    }
    __syncthreads();
    for (int r = ty; r < 32; r += 8) {
        float v = t[tx][r];
        bf16 hi = __float2bfloat16(v);
        size_t o = (size_t)(n0 + r)*K + k0 + tx;
        dhi[o] = hi;
        if (dlo) dlo[o] = __float2bfloat16(v - __bfloat162float(hi));
    }
}

#define T_WG 1248
#define T_WP (T_WG + 416)
#define T_WB (T_WP + 112)
#define T_WW (T_WB + 48)
#define T_WM (T_WW + 8)
#define T_KW (T_WM + 64)
#define T_UN (T_KW + 256)
#define T_ALL (T_UN + 1)

__global__ __launch_bounds__(256) void k_prep(
    const float* __restrict__ W_full, const float* __restrict__ W_full2,
    const float* __restrict__ W_fc,   const float* __restrict__ W_fc1,
    const float* __restrict__ keys,   const float* __restrict__ vec_a,
    const float* __restrict__ u) {
    int blk = blockIdx.x, tid = threadIdx.x;
    if (blk < T_WG) {
        tsplit_tile(W_full, g_WG_hi, g_WG_lo, CAT0, GN, CAT0, 0, blk, tid);
    } else if (blk < T_WP) {
        tsplit_tile(W_full2, g_WP_hi, g_WP_lo, CAT0, HS, CAT0, 0, blk - T_WG, tid);
    } else if (blk < T_WB) {
        tsplit_tile(W_fc, g_Wb_hi, nullptr, XCU, 128, 768, 128, blk - T_WP, tid);
    } else if (blk < T_WW) {
        tsplit_tile(W_fc1, g_Ww_hi, g_Ww_lo, 768, 64, 768, 0, blk - T_WB, tid);
    } else if (blk < T_WM) {
        tsplit_tile(W_fc + 832*128, g_Wm_hi, nullptr, 64, 128, 64, 0, blk - T_WW, tid);
    } else if (blk < T_KW) {
        __shared__ float krow[2][64];
        int sub = tid >> 7, t = tid & 127;
        int m = (blk - T_WM)*2 + sub;
        if (t < 64) krow[sub][t] = keys[m*64 + t];
        __syncthreads();
        float acc = 0.f;
        #pragma unroll 8
        for (int r = 0; r < 64; r++) acc += krow[sub][r] * W_fc[(768+r)*128 + t];
        g_keyW[m*128 + t] = acc;
    } else if (blk < T_UN) {
        int w = tid >> 5, lane = tid & 31;
        int b = (blk - T_KW)*8 + w;
        float s = 0.f;
        #pragma unroll
        for (int j = lane; j < 128; j += 32) { float v = u[b*128+j]; s += v*v; }
        #pragma unroll
        for (int o = 16; o > 0; o >>= 1) s += __shfl_down_sync(0xffffffffu, s, o);
        if (lane == 0) g_uinv[b] = 1.f / fmaxf(sqrtf(s), 1e-12f);
    } else {
        if (tid < 128) g_veca[tid] = vec_a[tid];
    }
}

// ---------------- k_gp: merged G+P GEMM, 128x64 tiles, 2 blocks/SM ----------------
// blockIdx.x < 24 -> G tile; else P tile (A scaled by alpha/beta).
// WM=2, WN=4, MF=4, NF=2; BK=32; 3-pass bf16 split; cp.async double-buffered B.
#define GP_NGX 24
#define GP_SMEM 61440
__global__ __launch_bounds__(256, 2) void k_gp(
    const float* __restrict__ x, const float* __restrict__ h,
    const float* __restrict__ biasG, const float* __restrict__ bias2) {
    constexpr int BK = 32, LDA = 40;
    constexpr int BM = 128, BN = 64, NT = 256;
    constexpr int ASZ = BM*LDA, BSZE = BN*LDA;
    constexpr int STAGE = (ASZ + BSZE) * 2;
    constexpr int MF = 4, NF = 2;
    extern __shared__ __align__(16) bf16 sm[];
    int tid = threadIdx.x;
    int w = tid >> 5, lane = tid & 31, g = lane >> 2, tg = lane & 3;
    int wm = w >> 2, wn = w & 3;
    bool isP = blockIdx.x >= GP_NGX;
    int n0 = (isP ? (int)blockIdx.x - GP_NGX : (int)blockIdx.x) * BN;
    int m0 = blockIdx.y * BM;
    const bf16* BT_hi = isP ? g_WP_hi : g_WG_hi;
    const bf16* BT_lo = isP ? g_WP_lo : g_WG_lo;
    const int KT = CAT0 / BK;
    float c[MF][NF][4] = {};

    uint32_t a_off = (uint32_t)(((((lane>>3)&1)*8 + (lane&7))*LDA + (lane>>4)*8) * 2);
    uint32_t b_off = (uint32_t)((((lane&7) + ((lane>>4)&1)*8)*LDA + ((lane>>3)&1)*8) * 2);

    float4 av[4];
    auto ldA = [&](int kt) {
        #pragma unroll
        for (int l = 0; l < 4; l++) {
            int i = tid + l*NT;
            int row = i >> 3, q = i & 7;
            int gr = m0 + row, kk = kt*BK + q*4;
            float4 v;
            if (kk < 256)      v = *(const float4*)&x[(size_t)gr*256 + kk];
            else if (kk < 768) v = *(const float4*)&h[(size_t)gr*512 + kk-256];
            else               v = *(const float4*)&g_r[(size_t)gr*64 + kk-768];
            if (isP) {
                float s = (kk >= 768) ? g_ab[gr*2+1] : (kk >= 256) ? g_ab[gr*2] : 1.f;
                v.x *= s; v.y *= s; v.z *= s; v.w *= s;
            }
            av[l] = v;
        }
    };
    auto stA = [&](int s) {
        bf16* Ah = sm + s*STAGE;
        bf16* Al = Ah + ASZ;
        #pragma unroll
        for (int l = 0; l < 4; l++) {
            int i = tid + l*NT;
            int row = i >> 3, q = i & 7;
            float4 v = av[l];
            uint32_t h0, l0, h1, l1;
            split2(v.x, v.y, h0, l0);
            split2(v.z, v.w, h1, l1);
            uint2 hh; hh.x = h0; hh.y = h1;
            uint2 ll; ll.x = l0; ll.y = l1;
            *(uint2*)&Ah[row*LDA + q*4] = hh;
            *(uint2*)&Al[row*LDA + q*4] = ll;
        }
    };
    auto ldB = [&](int s, int kt) {
        bf16* Bh = sm + s*STAGE + ASZ*2;
        bf16* Bl = Bh + BSZE;
        int i = tid;
        int r = i >> 2, q = i & 3;
        CP_ASYNC16(sptr(&Bh[r*LDA + q*8]), &BT_hi[(size_t)(n0+r)*CAT0 + kt*BK + q*8]);
        CP_ASYNC16(sptr(&Bl[r*LDA + q*8]), &BT_lo[(size_t)(n0+r)*CAT0 + kt*BK + q*8]);
    };

    ldA(0); ldB(0, 0); CP_COMMIT(); stA(0);
    CP_WAIT0(); __syncthreads();

    for (int kt = 0; kt < KT; kt++) {
        int s = kt & 1;
        bool nxt = (kt + 1 < KT);
        if (nxt) { ldB(s^1, kt+1); CP_COMMIT(); ldA(kt+1); }

        uint32_t ahb = sptr(sm + s*STAGE) + (uint32_t)(wm*MF*16*LDA*2) + a_off;
        uint32_t alb = ahb + (uint32_t)(ASZ*2);
        uint32_t bhb = sptr(sm + s*STAGE + ASZ*2) + (uint32_t)(wn*NF*8*LDA*2) + b_off;
        uint32_t blb = bhb + (uint32_t)(BSZE*2);
        #pragma unroll
        for (int k0 = 0; k0 < BK; k0 += 16) {
            uint32_t ah[MF][4], al[MF][4];
            #pragma unroll
            for (int mf = 0; mf < MF; mf++) {
                LDSM_X4(ah[mf], ahb + (uint32_t)((mf*16*LDA + k0)*2));
                LDSM_X4(al[mf], alb + (uint32_t)((mf*16*LDA + k0)*2));
            }
            uint32_t bh[4], bl[4];
            LDSM_X4(bh, bhb + (uint32_t)(k0*2));
            LDSM_X4(bl, blb + (uint32_t)(k0*2));
            #pragma unroll
            for (int mf = 0; mf < MF; mf++) {
                mma_bf16(c[mf][0], ah[mf], bh[0], bh[1]);
                mma_bf16(c[mf][1], ah[mf], bh[2], bh[3]);
                mma_bf16(c[mf][0], al[mf], bh[0], bh[1]);
                mma_bf16(c[mf][1], al[mf], bh[2], bh[3]);
                mma_bf16(c[mf][0], ah[mf], bl[0], bl[1]);
                mma_bf16(c[mf][1], ah[mf], bl[2], bl[3]);
            }
        }
        if (nxt) stA(s^1);
        CP_WAIT0(); __syncthreads();
    }

    float* C = isP ? g_P : g_G;
    const float* bias = isP ? bias2 : biasG;
    int N = isP ? HS : GN;
    #pragma unroll
    for (int mf = 0; mf < MF; mf++) {
        int r0 = m0 + wm*MF*16 + mf*16 + g;
        #pragma unroll
        for (int nf = 0; nf < NF; nf++) {
            int cb = n0 + wn*NF*8 + nf*8 + 2*tg;
            C[(size_t)r0*N + cb]       = c[mf][nf][0] + bias[cb];
            C[(size_t)r0*N + cb + 1]   = c[mf][nf][1] + bias[cb+1];
            C[(size_t)(r0+8)*N + cb]   = c[mf][nf][2] + bias[cb];
            C[(size_t)(r0+8)*N + cb+1] = c[mf][nf][3] + bias[cb+1];
        }
    }
}

// ---------------- generic pipelined GEMM (base / hw) ----------------
template<int WM, int WN, int MF, int NF, int SRC, int PASSES, int OUTM>
__global__ __launch_bounds__(WM*WN*32) void mgemm(
    const float* __restrict__ p0, const float* __restrict__ p1,
    const float* __restrict__ p2, const float* __restrict__ aux,
    const bf16* __restrict__ BT_hi, const bf16* __restrict__ BT_lo,
    float* __restrict__ C, const float* __restrict__ bias,
    const int* __restrict__ memcnt, int N, int K) {
    constexpr int BK = 32, LDA = 40;
    constexpr int BM = WM*MF*16, BN = WN*NF*8, NT = WM*WN*32;
    constexpr int NBUF = (PASSES > 1) ? 2 : 1;
    constexpr int ASZ = BM*LDA, BSZE = BN*LDA;
    constexpr int STAGE = (ASZ + BSZE) * NBUF;
    constexpr int ALOADS = BM*BK/4/NT;
    constexpr int BCHUNK = BN*BK/8/NT;
    extern __shared__ __align__(16) bf16 sm[];
    int tid = threadIdx.x;
    int w = tid >> 5, lane = tid & 31, g = lane >> 2, tg = lane & 3;
    int wm = w / WN, wn = w % WN;
    int m0 = blockIdx.y*BM, n0 = blockIdx.x*BN;
    const int KT = K / BK;
    float c[MF][NF][4] = {};

    uint32_t a_off = (uint32_t)(((((lane>>3)&1)*8 + (lane&7))*LDA + (lane>>4)*8) * 2);
    uint32_t b_off = (uint32_t)((((lane&7) + ((lane>>4)&1)*8)*LDA + ((lane>>3)&1)*8) * 2);

    float4 av[ALOADS];
    auto ldA = [&](int kt) {
        #pragma unroll
        for (int l = 0; l < ALOADS; l++) {
            int i = tid + l*NT;
            int row = i/(BK/4), q = i%(BK/4);
            int gr = m0 + row, kk = kt*BK + q*4;
            float4 v;
            if (SRC == 2) {
                if (kk < 256)      v = *(const float4*)&p0[(size_t)gr*256 + kk];
                else if (kk < 768) v = *(const float4*)&p1[(size_t)gr*512 + kk-256];
                else {
                    v = *(const float4*)&p2[(size_t)gr*128 + kk-768];
                    float s = aux[gr];
                    v.x *= s; v.y *= s; v.z *= s; v.w *= s;
                }
            } else {
                if (kk < 256)      v = *(const float4*)&p0[(size_t)gr*256 + kk];
                else               v = *(const float4*)&p1[(size_t)gr*OC + kk-256];
            }
            av[l] = v;
        }
    };
    auto stA = [&](int s) {
        bf16* Ah = sm + s*STAGE;
        bf16* Al = Ah + ASZ;
        #pragma unroll
        for (int l = 0; l < ALOADS; l++) {
            int i = tid + l*NT;
            int row = i/(BK/4), q = i%(BK/4);
            float4 v = av[l];
            if (PASSES > 1) {
                uint32_t h0, l0, h1, l1;
                split2(v.x, v.y, h0, l0);
                split2(v.z, v.w, h1, l1);
                uint2 hh; hh.x = h0; hh.y = h1;
                uint2 ll; ll.x = l0; ll.y = l1;
                *(uint2*)&Ah[row*LDA + q*4] = hh;
                *(uint2*)&Al[row*LDA + q*4] = ll;
            } else {
                uint2 hh; hh.x = pack_hi2(v.x, v.y); hh.y = pack_hi2(v.z, v.w);
                *(uint2*)&Ah[row*LDA + q*4] = hh;
            }
        }
    };
    auto ldB = [&](int s, int kt) {
        bf16* Bh = sm + s*STAGE + ASZ*NBUF;
        bf16* Bl = Bh + BSZE;
        #pragma unroll
        for (int l = 0; l < BCHUNK; l++) {
            int i = tid + l*NT;
            int r = i/(BK/8), q = i%(BK/8);
            CP_ASYNC16(sptr(&Bh[r*LDA + q*8]), &BT_hi[(size_t)(n0+r)*K + kt*BK + q*8]);
            if (PASSES > 1)
                CP_ASYNC16(sptr(&Bl[r*LDA + q*8]), &BT_lo[(size_t)(n0+r)*K + kt*BK + q*8]);
        }
    };

    ldA(0); ldB(0, 0); CP_COMMIT(); stA(0);
    CP_WAIT0(); __syncthreads();

    for (int kt = 0; kt < KT; kt++) {
        int s = kt & 1;
        bool nxt = (kt + 1 < KT);
        if (nxt) { ldB(s^1, kt+1); CP_COMMIT(); ldA(kt+1); }

        uint32_t ahb = sptr(sm + s*STAGE) + (uint32_t)(wm*MF*16*LDA*2) + a_off;
        uint32_t alb = ahb + (uint32_t)(ASZ*2);
        uint32_t bhb = sptr(sm + s*STAGE + ASZ*NBUF) + (uint32_t)(wn*NF*8*LDA*2) + b_off;
        uint32_t blb = bhb + (uint32_t)(BSZE*2);
        #pragma unroll
        for (int k0 = 0; k0 < BK; k0 += 16) {
            uint32_t ah[MF][4], al[MF][4];
            #pragma unroll
            for (int mf = 0; mf < MF; mf++) {
                LDSM_X4(ah[mf], ahb + (uint32_t)((mf*16*LDA + k0)*2));
                if (PASSES > 1)
                    LDSM_X4(al[mf], alb + (uint32_t)((mf*16*LDA + k0)*2));
            }
            #pragma unroll
            for (int np = 0; np < NF/2; np++) {
                uint32_t bh[4];
                LDSM_X4(bh, bhb + (uint32_t)((np*16*LDA + k0)*2));
                #pragma unroll
                for (int mf = 0; mf < MF; mf++) {
                    mma_bf16(c[mf][2*np],   ah[mf], bh[0], bh[1]);
                    mma_bf16(c[mf][2*np+1], ah[mf], bh[2], bh[3]);
                }
                if (PASSES > 1) {
                    uint32_t bl[4];
                    LDSM_X4(bl, blb + (uint32_t)((np*16*LDA + k0)*2));
                    #pragma unroll
                    for (int mf = 0; mf < MF; mf++) {
                        mma_bf16(c[mf][2*np],   al[mf], bh[0], bh[1]);
                        mma_bf16(c[mf][2*np+1], al[mf], bh[2], bh[3]);
                        mma_bf16(c[mf][2*np],   ah[mf], bl[0], bl[1]);
                        mma_bf16(c[mf][2*np+1], ah[mf], bl[2], bl[3]);
                    }
                }
            }
        }
        if (nxt) stA(s^1);
        CP_WAIT0(); __syncthreads();
    }

    int mc = OUTM ? memcnt[0] : 0;
    #pragma unroll
    for (int mf = 0; mf < MF; mf++) {
        int r0 = m0 + wm*MF*16 + mf*16 + g;
        #pragma unroll
        for (int nf = 0; nf < NF; nf++) {
            int cb = n0 + wn*NF*8 + nf*8 + 2*tg;
            float v0 = c[mf][nf][0] + bias[cb];
            float v1 = c[mf][nf][1] + bias[cb+1];
            float v2 = c[mf][nf][2] + bias[cb];
            float v3 = c[mf][nf][3] + bias[cb+1];
            if (OUTM) {
                int row0 = (mc < MS) ? mc : g_idx[r0];
                int row1 = (mc < MS) ? mc : g_idx[r0+8];
                float* d0 = &C[((size_t)r0*MS + row0)*RS];
                float* d1 = &C[((size_t)(r0+8)*MS + row1)*RS];
                d0[cb] = v0; d0[cb+1] = v1;
                d1[cb] = v2; d1[cb+1] = v3;
            } else {
                C[(size_t)r0*N + cb]       = v0;
                C[(size_t)r0*N + cb + 1]   = v1;
                C[(size_t)(r0+8)*N + cb]   = v2;
                C[(size_t)(r0+8)*N + cb+1] = v3;
            }
        }
    }
}

// ---------------- k_hid_mma (unchanged from R5) ----------------
__global__ __launch_bounds__(256) void k_hid_mma(
    const float* __restrict__ hmem, float* __restrict__ out_hmem,
    const float* __restrict__ prev, const float* __restrict__ nsm,
    const float* __restrict__ x, const float* __restrict__ h,
    const float* __restrict__ W1, const float* __restrict__ b1,
    const float* __restrict__ nsig, float* __restrict__ d_out) {
    constexpr int LDA = 72;
    __shared__ __align__(16) bf16 As_hi[128*LDA];
    __shared__ __align__(16) bf16 Bs_hi[128*LDA];
    __shared__ float s_base[128], s_veca[128], s_head[128];
    __shared__ float red[256], red1[256];
    __shared__ float sv[128];
    __shared__ int   si[128];
    __shared__ float sh_r[64];
    int tid = threadIdx.x;
    int w = tid >> 5, lane = tid & 31, g = lane >> 2, tg = lane & 3;
    int wm = w >> 2, wn = w & 3;
    int b = blockIdx.x;

    const float4* src = (const float4*)(hmem + (size_t)b*8192);
    float4*       dst = (float4*)(out_hmem + (size_t)b*8192);
    for (int i = tid; i < 2048; i += 256) {
        float4 v = src[i];
        dst[i] = v;
        int row = i >> 4, c4 = (i & 15) * 4;
        uint2 hh; hh.x = pack_hi2(v.x, v.y); hh.y = pack_hi2(v.z, v.w);
        *(uint2*)&As_hi[row*LDA + c4] = hh;
    }
    for (int i = tid; i < 1024; i += 256) {
        int r = i >> 3, q = i & 7;
        *(uint4*)&Bs_hi[r*LDA + q*8] = *(const uint4*)&g_Wm_hi[r*64 + q*8];
    }
    if (tid < 128) {
        s_base[tid] = g_base[(size_t)b*128 + tid];
        s_veca[tid] = g_veca[tid];
        s_head[tid] = 0.f;
    }
    __syncthreads();

    uint32_t a_lane_off = (uint32_t)(((((lane>>3)&1)*8 + (lane&7))*LDA + (lane>>4)*8) * 2);
    uint32_t as_base = sptr(As_hi) + (uint32_t)(wm*64*LDA*2) + a_lane_off;

    float c[4][4][4] = {};
    #pragma unroll
    for (int k0 = 0; k0 < 64; k0 += 16) {
        uint32_t ah[4][4];
        #pragma unroll
        for (int mf = 0; mf < 4; mf++)
            LDSM_X4(ah[mf], as_base + (uint32_t)((mf*16*LDA + k0)*2));
        #pragma unroll
        for (int nf = 0; nf < 4; nf++) {
            int nb = wn*32 + nf*8 + g;
            uint32_t bh0 = *(uint32_t*)&Bs_hi[nb*LDA + k0 + 2*tg];
            uint32_t bh1 = *(uint32_t*)&Bs_hi[nb*LDA + k0 + 8 + 2*tg];
            #pragma unroll
            for (int mf = 0; mf < 4; mf++) mma_bf16(c[mf][nf], ah[mf], bh0, bh1);
        }
    }

    #pragma unroll
    for (int mf = 0; mf < 4; mf++) {
        int r0 = wm*64 + mf*16 + g, r1 = r0 + 8;
        float hs0 = 0.f, hs1 = 0.f;
        #pragma unroll
        for (int nf = 0; nf < 4; nf++) {
            int cb = wn*32 + nf*8 + 2*tg;
            float v;
            v = c[mf][nf][0] + s_base[cb]   + g_keyW[r0*128 + cb];   hs0 += tanh_fast(v)*s_veca[cb];
            v = c[mf][nf][1] + s_base[cb+1] + g_keyW[r0*128 + cb+1]; hs0 += tanh_fast(v)*s_veca[cb+1];
            v = c[mf][nf][2] + s_base[cb]   + g_keyW[r1*128 + cb];   hs1 += tanh_fast(v)*s_veca[cb];
            v = c[mf][nf][3] + s_base[cb+1] + g_keyW[r1*128 + cb+1]; hs1 += tanh_fast(v)*s_veca[cb+1];
        }
        atomicAdd(&s_head[r0], hs0);
        atomicAdd(&s_head[r1], hs1);
    }
    __syncthreads();

    int t = tid;
    float val = 0.f;
    if (t < 128) {
        val = s_head[t] - 100.f * prev[b*128 + t];
        red[t] = val * val;
    }
    __syncthreads();
    if (t < 64) red[t] += red[t+64];
    __syncthreads();
    for (int s = 32; s > 0; s >>= 1) { if (t < s) red[t] += red[t+s]; __syncthreads(); }
    if (t < 128) {
        float norm = fmaxf(sqrtf(red[0]), 1e-12f);
        sv[t] = val / norm + gumbel(nsm[b*128 + t]);
        si[t] = t;
    }
    __syncthreads();
    for (int s = 64; s > 0; s >>= 1) {
        if (t < s && sv[t+s] > sv[t]) { sv[t] = sv[t+s]; si[t] = si[t+s]; }
        __syncthreads();
    }
    int best = si[0];
    if (t == 0) g_idx[b] = best;
    if (t < 64) {
        float rv = hmem[((size_t)b*128 + best)*64 + t];
        g_r[b*64 + t] = rv;
        sh_r[t] = rv;
        d_out[(size_t)b*OC + 512 + t] = rv;
    }
    __syncthreads();
    float s0 = 0.f, s1 = 0.f;
    for (int k = t; k < CAT0; k += 256) {
        float a = (k < 256) ? x[b*256+k] : (k < 768) ? h[b*512 + (k-256)] : sh_r[k-768];
        s0 += a * W1[k*2];
        s1 += a * W1[k*2 + 1];
    }
    red[t] = s0; red1[t] = s1;
    __syncthreads();
    for (int s = 128; s > 0; s >>= 1) {
        if (t < s) { red[t] += red[t+s]; red1[t] += red1[t+s]; }
        __syncthreads();
    }
    if (t == 0) {
        const float ST = (float)(10.0/3.0);
        g_ab[b*2]     = sigm((red[0]  + b1[0] + gumbel(nsig[b*2]))   * ST);
        g_ab[b*2 + 1] = sigm((red1[0] + b1[1] + gumbel(nsig[b*2+1])) * ST);
    }
}

// ---------------- k_ep ----------------
__global__ void k_ep(const float* __restrict__ c, float* __restrict__ d_out) {
    int gid = blockIdx.x * blockDim.x + threadIdx.x;
    int b = gid >> 9, j = gid & 511;
    float i_ = g_G[(size_t)b*GN + j];
    float f_ = g_G[(size_t)b*GN + 512 + j];
    float o_ = g_G[(size_t)b*GN + 1024 + j];
    float p  = g_P[(size_t)b*HS + j];
    float nc = c[gid] * sigm(f_ + 1.f) + sigm(i_) * tanhf(p);
    float nh = tanhf(nc) * sigm(o_);
    d_out[(size_t)b*OC + j] = nh;
}

// ---------------- launch ----------------
extern "C" void kernel_launch(void* const* d_in, const int* in_sizes, int n_in,
                              void* d_out, int out_size) {
    const float* x        = (const float*)d_in[0];
    const float* h        = (const float*)d_in[1];
    const float* c        = (const float*)d_in[2];
    const float* hmem     = (const float*)d_in[3];
    const float* u_t      = (const float*)d_in[4];
    const float* prev     = (const float*)d_in[5];
    const float* W_full   = (const float*)d_in[6];
    const float* bias     = (const float*)d_in[7];
    const float* W_full1  = (const float*)d_in[8];
    const float* bias1    = (const float*)d_in[9];
    const float* W_full2  = (const float*)d_in[10];
    const float* bias2    = (const float*)d_in[11];
    const float* keys     = (const float*)d_in[12];
    const float* vec_a    = (const float*)d_in[13];
    const float* W_fc     = (const float*)d_in[14];
    const float* b_fc     = (const float*)d_in[15];
    const float* W_fc1    = (const float*)d_in[16];
    const float* b_fc1    = (const float*)d_in[17];
    const float* noise_sm = (const float*)d_in[18];
    const float* noise_sig= (const float*)d_in[19];
    const int*   memcnt   = (const int*)d_in[20];

    float* out      = (float*)d_out;
    float* out_hmem = out + (size_t)BSZ * OC;

    float *pbase, *puinv;
    bf16 *pWbh, *pWwh, *pWwl;
    cudaGetSymbolAddress((void**)&pbase, g_base);
    cudaGetSymbolAddress((void**)&puinv, g_uinv);
    cudaGetSymbolAddress((void**)&pWbh,  g_Wb_hi);
    cudaGetSymbolAddress((void**)&pWwh,  g_Ww_hi);
    cudaGetSymbolAddress((void**)&pWwl,  g_Ww_lo);

    auto kBase = mgemm<2,4,1,2, 2,1, 0>;  // 32x64 tile, 1-pass
    auto kHw   = mgemm<2,2,1,4, 3,3, 1>;  // 32x64 tile, 3-pass, hmem scatter
    cudaFuncSetAttribute((const void*)k_gp,  cudaFuncAttributeMaxDynamicSharedMemorySize, GP_SMEM);
    cudaFuncSetAttribute((const void*)kBase, cudaFuncAttributeMaxDynamicSharedMemorySize, 15360);
    cudaFuncSetAttribute((const void*)kHw,   cudaFuncAttributeMaxDynamicSharedMemorySize, 30720);

    // 1. all prep
    k_prep<<<T_ALL, 256>>>(W_full, W_full2, W_fc, W_fc1, keys, vec_a, u_t);
    // 2. base = [x,c,u^]@Wb + b_fc
    kBase<<<dim3(2, BSZ/32), 256, 15360>>>(
        x, c, u_t, puinv, pWbh, pWbh, pbase, b_fc, nullptr, 128, XCU);
    // 3. hid + head + argmax + r + ab + hmem copy
    k_hid_mma<<<BSZ, 256>>>(hmem, out_hmem, prev, noise_sm, x, h, W_full1, bias1, noise_sig, out);
    // 4. merged G + P GEMM (512 blocks, 2/SM)
    k_gp<<<dim3(GP_NGX + HS/64, BSZ/128), 256, GP_SMEM>>>(x, h, bias, bias2);
    // 5. LSTM epilogue -> new_h
    k_ep<<<(BSZ*HS)/256, 256>>>(c, out);
    // 6. h_w = [x,new_h]@W_fc1 + b_fc1 -> scatter into out_hmem rows
    kHw<<<dim3(1, BSZ/32), 128, 30720>>>(
        x, out, nullptr, nullptr, pWwh, pWwl, out_hmem, b_fc1, memcnt, 64, 768);
    (void)in_sizes; (void)n_in; (void)out_size;
}

// round 7
// speedup vs baseline: 2.8295x; 1.0068x over previous
#include <cuda_runtime.h>
#include <cuda_bf16.h>
#include <math.h>
#include <stdint.h>

#define BSZ 2048
#define HS  512
#define RS  64
#define MS  128
#define CAT0 832
#define XCU 896
#define GN  1536
#define OC  576

typedef __nv_bfloat16 bf16;

// ---------------- scratch (device globals; no allocations) ----------------
__device__ __align__(16) float g_base [BSZ*128];
__device__ __align__(16) float g_keyW [128*128];
__device__ __align__(16) float g_ab   [BSZ*2];
__device__             int   g_idx  [BSZ];
__device__ __align__(16) float g_r    [BSZ*RS];
__device__ __align__(16) float g_G    [BSZ*GN];
__device__ __align__(16) float g_P    [BSZ*HS];
__device__ __align__(16) float g_veca [128];
__device__ __align__(16) float g_uinv [BSZ];
__device__ __align__(16) bf16 g_WG_hi[GN*CAT0],  g_WG_lo[GN*CAT0];
__device__ __align__(16) bf16 g_WP_hi[HS*CAT0],  g_WP_lo[HS*CAT0];
__device__ __align__(16) bf16 g_Wb_hi[128*XCU];
__device__ __align__(16) bf16 g_Ww_hi[64*768],   g_Ww_lo[64*768];
__device__ __align__(16) bf16 g_Wm_hi[128*64];

__device__ __forceinline__ float tanh_fast(float x) {
    float y; asm("tanh.approx.f32 %0, %1;" : "=f"(y) : "f"(x)); return y;
}
__device__ __forceinline__ float sigm(float x) { return 1.f/(1.f+expf(-x)); }
__device__ __forceinline__ float gumbel(float u) {
    return -logf(1e-20f - logf(1e-20f + u));
}
__device__ __forceinline__ void split2(float a, float b, uint32_t& hi, uint32_t& lo) {
    __nv_bfloat162 h, l;
    h.x = __float2bfloat16(a); h.y = __float2bfloat16(b);
    l.x = __float2bfloat16(a - __bfloat162float(h.x));
    l.y = __float2bfloat16(b - __bfloat162float(h.y));
    hi = *(uint32_t*)&h; lo = *(uint32_t*)&l;
}
__device__ __forceinline__ uint32_t pack_hi2(float a, float b) {
    __nv_bfloat162 h; h.x = __float2bfloat16(a); h.y = __float2bfloat16(b);
    return *(uint32_t*)&h;
}
__device__ __forceinline__ void mma_bf16(float* c, const uint32_t* a, uint32_t b0, uint32_t b1) {
    asm volatile("mma.sync.aligned.m16n8k16.row.col.f32.bf16.bf16.f32 "
        "{%0,%1,%2,%3},{%4,%5,%6,%7},{%8,%9},{%0,%1,%2,%3};"
        : "+f"(c[0]), "+f"(c[1]), "+f"(c[2]), "+f"(c[3])
        : "r"(a[0]), "r"(a[1]), "r"(a[2]), "r"(a[3]), "r"(b0), "r"(b1));
}
#define LDSM_X4(r, addr) \
    asm volatile("ldmatrix.sync.aligned.m8n8.x4.shared.b16 {%0,%1,%2,%3}, [%4];" \
        : "=r"((r)[0]), "=r"((r)[1]), "=r"((r)[2]), "=r"((r)[3]) : "r"(addr))
#define CP_ASYNC16(saddr, gptr) \
    asm volatile("cp.async.cg.shared.global [%0], [%1], 16;" :: "r"(saddr), "l"(gptr))
#define CP_COMMIT() asm volatile("cp.async.commit_group;" ::: "memory")
#define CP_WAIT0()  asm volatile("cp.async.wait_group 0;" ::: "memory")
__device__ __forceinline__ uint32_t sptr(const void* p) {
    return (uint32_t)__cvta_generic_to_shared(p);
}

// ---------------- k_prep ----------------
__device__ void tsplit_tile(const float* __restrict__ src, bf16* __restrict__ dhi,
                            bf16* __restrict__ dlo, int K, int N, int split, int extra,
                            int tile, int tid) {
    __shared__ float t[32][33];
    int nt = N/32;
    int n0 = (tile % nt)*32, k0 = (tile / nt)*32;
    int tx = tid & 31, ty = tid >> 5;
    for (int r = ty; r < 32; r += 8) {
        int k = k0 + r; int sr = (k < split) ? k : k + extra;
        t[r][tx] = src[(size_t)sr*N + n0 + tx];
    }
    __syncthreads();
    for (int r = ty; r < 32; r += 8) {
        float v = t[tx][r];
        bf16 hi = __float2bfloat16(v);
        size_t o = (size_t)(n0 + r)*K + k0 + tx;
        dhi[o] = hi;
        if (dlo) dlo[o] = __float2bfloat16(v - __bfloat162float(hi));
    }
}

#define T_WG 1248
#define T_WP (T_WG + 416)
#define T_WB (T_WP + 112)
#define T_WW (T_WB + 48)
#define T_WM (T_WW + 8)
#define T_KW (T_WM + 64)
#define T_UN (T_KW + 256)
#define T_ALL (T_UN + 1)

__global__ __launch_bounds__(256) void k_prep(
    const float* __restrict__ W_full, const float* __restrict__ W_full2,
    const float* __restrict__ W_fc,   const float* __restrict__ W_fc1,
    const float* __restrict__ keys,   const float* __restrict__ vec_a,
    const float* __restrict__ u) {
    int blk = blockIdx.x, tid = threadIdx.x;
    if (blk < T_WG) {
        tsplit_tile(W_full, g_WG_hi, g_WG_lo, CAT0, GN, CAT0, 0, blk, tid);
    } else if (blk < T_WP) {
        tsplit_tile(W_full2, g_WP_hi, g_WP_lo, CAT0, HS, CAT0, 0, blk - T_WG, tid);
    } else if (blk < T_WB) {
        tsplit_tile(W_fc, g_Wb_hi, nullptr, XCU, 128, 768, 128, blk - T_WP, tid);
    } else if (blk < T_WW) {
        tsplit_tile(W_fc1, g_Ww_hi, g_Ww_lo, 768, 64, 768, 0, blk - T_WB, tid);
    } else if (blk < T_WM) {
        tsplit_tile(W_fc + 832*128, g_Wm_hi, nullptr, 64, 128, 64, 0, blk - T_WW, tid);
    } else if (blk < T_KW) {
        __shared__ float krow[2][64];
        int sub = tid >> 7, t = tid & 127;
        int m = (blk - T_WM)*2 + sub;
        if (t < 64) krow[sub][t] = keys[m*64 + t];
        __syncthreads();
        float acc = 0.f;
        #pragma unroll 8
        for (int r = 0; r < 64; r++) acc += krow[sub][r] * W_fc[(768+r)*128 + t];
        g_keyW[m*128 + t] = acc;
    } else if (blk < T_UN) {
        int w = tid >> 5, lane = tid & 31;
        int b = (blk - T_KW)*8 + w;
        float s = 0.f;
        #pragma unroll
        for (int j = lane; j < 128; j += 32) { float v = u[b*128+j]; s += v*v; }
        #pragma unroll
        for (int o = 16; o > 0; o >>= 1) s += __shfl_down_sync(0xffffffffu, s, o);
        if (lane == 0) g_uinv[b] = 1.f / fmaxf(sqrtf(s), 1e-12f);
    } else {
        if (tid < 128) g_veca[tid] = vec_a[tid];
    }
}

// ---------------- k_gp: merged G+P GEMM + interleaved hmem copy ----------------
// WM=4, WN=2 (MF=2, NF=4): 128x64 tile, A-fragment redundancy 2x (was 4x).
// Each block also copies 8192 float4 (32KB) of hmem -> out_hmem, software-pipelined.
#define GP_NGX 24
#define GP_SMEM 61440
__global__ __launch_bounds__(256, 2) void k_gp(
    const float* __restrict__ x, const float* __restrict__ h,
    const float* __restrict__ biasG, const float* __restrict__ bias2,
    const float* __restrict__ hmem, float* __restrict__ out_hmem) {
    constexpr int BK = 32, LDA = 40;
    constexpr int BM = 128, BN = 64, NT = 256;
    constexpr int ASZ = BM*LDA, BSZE = BN*LDA;
    constexpr int STAGE = (ASZ + BSZE) * 2;
    constexpr int MF = 2, NF = 4;
    extern __shared__ __align__(16) bf16 sm[];
    int tid = threadIdx.x;
    int w = tid >> 5, lane = tid & 31, g = lane >> 2, tg = lane & 3;
    int wm = w >> 1, wn = w & 1;
    bool isP = blockIdx.x >= GP_NGX;
    int n0 = (isP ? (int)blockIdx.x - GP_NGX : (int)blockIdx.x) * BN;
    int m0 = blockIdx.y * BM;
    const bf16* BT_hi = isP ? g_WP_hi : g_WG_hi;
    const bf16* BT_lo = isP ? g_WP_lo : g_WG_lo;
    const int KT = CAT0 / BK;   // 26
    float c[MF][NF][4] = {};

    // distributed hmem copy: 8192 float4 per block, 512 per k-iteration (16 iters)
    size_t cbase = ((size_t)(blockIdx.y * gridDim.x + blockIdx.x)) * 8192;
    const float4* csrc = (const float4*)hmem;
    float4* cdst = (float4*)out_hmem;
    float4 cb0, cb1;

    uint32_t a_off = (uint32_t)(((((lane>>3)&1)*8 + (lane&7))*LDA + (lane>>4)*8) * 2);
    uint32_t b_off = (uint32_t)((((lane&7) + ((lane>>4)&1)*8)*LDA + ((lane>>3)&1)*8) * 2);

    float4 av[4];
    auto ldA = [&](int kt) {
        #pragma unroll
        for (int l = 0; l < 4; l++) {
            int i = tid + l*NT;
            int row = i >> 3, q = i & 7;
            int gr = m0 + row, kk = kt*BK + q*4;
            float4 v;
            if (kk < 256)      v = *(const float4*)&x[(size_t)gr*256 + kk];
            else if (kk < 768) v = *(const float4*)&h[(size_t)gr*512 + kk-256];
            else               v = *(const float4*)&g_r[(size_t)gr*64 + kk-768];
            if (isP) {
                float s = (kk >= 768) ? g_ab[gr*2+1] : (kk >= 256) ? g_ab[gr*2] : 1.f;
                v.x *= s; v.y *= s; v.z *= s; v.w *= s;
            }
            av[l] = v;
        }
    };
    auto stA = [&](int s) {
        bf16* Ah = sm + s*STAGE;
        bf16* Al = Ah + ASZ;
        #pragma unroll
        for (int l = 0; l < 4; l++) {
            int i = tid + l*NT;
            int row = i >> 3, q = i & 7;
            float4 v = av[l];
            uint32_t h0, l0, h1, l1;
            split2(v.x, v.y, h0, l0);
            split2(v.z, v.w, h1, l1);
            uint2 hh; hh.x = h0; hh.y = h1;
            uint2 ll; ll.x = l0; ll.y = l1;
            *(uint2*)&Ah[row*LDA + q*4] = hh;
            *(uint2*)&Al[row*LDA + q*4] = ll;
        }
    };
    auto ldB = [&](int s, int kt) {
        bf16* Bh = sm + s*STAGE + ASZ*2;
        bf16* Bl = Bh + BSZE;
        int r = tid >> 2, q = tid & 3;
        CP_ASYNC16(sptr(&Bh[r*LDA + q*8]), &BT_hi[(size_t)(n0+r)*CAT0 + kt*BK + q*8]);
        CP_ASYNC16(sptr(&Bl[r*LDA + q*8]), &BT_lo[(size_t)(n0+r)*CAT0 + kt*BK + q*8]);
    };

    ldA(0); ldB(0, 0); CP_COMMIT(); stA(0);
    // prime copy pipeline
    cb0 = csrc[cbase + tid];
    cb1 = csrc[cbase + 256 + tid];
    CP_WAIT0(); __syncthreads();

    for (int kt = 0; kt < KT; kt++) {
        int s = kt & 1;
        bool nxt = (kt + 1 < KT);
        if (nxt) { ldB(s^1, kt+1); CP_COMMIT(); ldA(kt+1); }
        // drain previous copy loads, issue next copy loads (latency hides under MMAs)
        if (kt < 16) {
            size_t o = cbase + (size_t)kt*512 + tid;
            cdst[o] = cb0;
            cdst[o + 256] = cb1;
            if (kt + 1 < 16) {
                size_t o2 = o + 512;
                cb0 = csrc[o2];
                cb1 = csrc[o2 + 256];
            }
        }

        uint32_t ahb = sptr(sm + s*STAGE) + (uint32_t)(wm*MF*16*LDA*2) + a_off;
        uint32_t alb = ahb + (uint32_t)(ASZ*2);
        uint32_t bhb = sptr(sm + s*STAGE + ASZ*2) + (uint32_t)(wn*NF*8*LDA*2) + b_off;
        uint32_t blb = bhb + (uint32_t)(BSZE*2);
        #pragma unroll
        for (int k0 = 0; k0 < BK; k0 += 16) {
            uint32_t ah[MF][4], al[MF][4];
            #pragma unroll
            for (int mf = 0; mf < MF; mf++) {
                LDSM_X4(ah[mf], ahb + (uint32_t)((mf*16*LDA + k0)*2));
                LDSM_X4(al[mf], alb + (uint32_t)((mf*16*LDA + k0)*2));
            }
            #pragma unroll
            for (int np = 0; np < NF/2; np++) {
                uint32_t bh[4], bl[4];
                LDSM_X4(bh, bhb + (uint32_t)((np*16*LDA + k0)*2));
                LDSM_X4(bl, blb + (uint32_t)((np*16*LDA + k0)*2));
                #pragma unroll
                for (int mf = 0; mf < MF; mf++) {
                    mma_bf16(c[mf][2*np],   ah[mf], bh[0], bh[1]);
                    mma_bf16(c[mf][2*np+1], ah[mf], bh[2], bh[3]);
                    mma_bf16(c[mf][2*np],   al[mf], bh[0], bh[1]);
                    mma_bf16(c[mf][2*np+1], al[mf], bh[2], bh[3]);
                    mma_bf16(c[mf][2*np],   ah[mf], bl[0], bl[1]);
                    mma_bf16(c[mf][2*np+1], ah[mf], bl[2], bl[3]);
                }
            }
        }
        if (nxt) stA(s^1);
        CP_WAIT0(); __syncthreads();
    }

    float* C = isP ? g_P : g_G;
    const float* bias = isP ? bias2 : biasG;
    int N = isP ? HS : GN;
    #pragma unroll
    for (int mf = 0; mf < MF; mf++) {
        int r0 = m0 + wm*MF*16 + mf*16 + g;
        #pragma unroll
        for (int nf = 0; nf < NF; nf++) {
            int cb = n0 + wn*NF*8 + nf*8 + 2*tg;
            C[(size_t)r0*N + cb]       = c[mf][nf][0] + bias[cb];
            C[(size_t)r0*N + cb + 1]   = c[mf][nf][1] + bias[cb+1];
            C[(size_t)(r0+8)*N + cb]   = c[mf][nf][2] + bias[cb];
            C[(size_t)(r0+8)*N + cb+1] = c[mf][nf][3] + bias[cb+1];
        }
    }
}

// ---------------- generic pipelined GEMM (base / hw) ----------------
template<int WM, int WN, int MF, int NF, int SRC, int PASSES, int OUTM>
__global__ __launch_bounds__(WM*WN*32) void mgemm(
    const float* __restrict__ p0, const float* __restrict__ p1,
    const float* __restrict__ p2, const float* __restrict__ aux,
    const bf16* __restrict__ BT_hi, const bf16* __restrict__ BT_lo,
    float* __restrict__ C, const float* __restrict__ bias,
    const int* __restrict__ memcnt, int N, int K) {
    constexpr int BK = 32, LDA = 40;
    constexpr int BM = WM*MF*16, BN = WN*NF*8, NT = WM*WN*32;
    constexpr int NBUF = (PASSES > 1) ? 2 : 1;
    constexpr int ASZ = BM*LDA, BSZE = BN*LDA;
    constexpr int STAGE = (ASZ + BSZE) * NBUF;
    constexpr int ALOADS = BM*BK/4/NT;
    constexpr int BCHUNK = BN*BK/8/NT;
    extern __shared__ __align__(16) bf16 sm[];
    int tid = threadIdx.x;
    int w = tid >> 5, lane = tid & 31, g = lane >> 2, tg = lane & 3;
    int wm = w / WN, wn = w % WN;
    int m0 = blockIdx.y*BM, n0 = blockIdx.x*BN;
    const int KT = K / BK;
    float c[MF][NF][4] = {};

    uint32_t a_off = (uint32_t)(((((lane>>3)&1)*8 + (lane&7))*LDA + (lane>>4)*8) * 2);
    uint32_t b_off = (uint32_t)((((lane&7) + ((lane>>4)&1)*8)*LDA + ((lane>>3)&1)*8) * 2);

    float4 av[ALOADS];
    auto ldA = [&](int kt) {
        #pragma unroll
        for (int l = 0; l < ALOADS; l++) {
            int i = tid + l*NT;
            int row = i/(BK/4), q = i%(BK/4);
            int gr = m0 + row, kk = kt*BK + q*4;
            float4 v;
            if (SRC == 2) {
                if (kk < 256)      v = *(const float4*)&p0[(size_t)gr*256 + kk];
                else if (kk < 768) v = *(const float4*)&p1[(size_t)gr*512 + kk-256];
                else {
                    v = *(const float4*)&p2[(size_t)gr*128 + kk-768];
                    float s = aux[gr];
                    v.x *= s; v.y *= s; v.z *= s; v.w *= s;
                }
            } else {
                if (kk < 256)      v = *(const float4*)&p0[(size_t)gr*256 + kk];
                else               v = *(const float4*)&p1[(size_t)gr*OC + kk-256];
            }
            av[l] = v;
        }
    };
    auto stA = [&](int s) {
        bf16* Ah = sm + s*STAGE;
        bf16* Al = Ah + ASZ;
        #pragma unroll
        for (int l = 0; l < ALOADS; l++) {
            int i = tid + l*NT;
            int row = i/(BK/4), q = i%(BK/4);
            float4 v = av[l];
            if (PASSES > 1) {
                uint32_t h0, l0, h1, l1;
                split2(v.x, v.y, h0, l0);
                split2(v.z, v.w, h1, l1);
                uint2 hh; hh.x = h0; hh.y = h1;
                uint2 ll; ll.x = l0; ll.y = l1;
                *(uint2*)&Ah[row*LDA + q*4] = hh;
                *(uint2*)&Al[row*LDA + q*4] = ll;
            } else {
                uint2 hh; hh.x = pack_hi2(v.x, v.y); hh.y = pack_hi2(v.z, v.w);
                *(uint2*)&Ah[row*LDA + q*4] = hh;
            }
        }
    };
    auto ldB = [&](int s, int kt) {
        bf16* Bh = sm + s*STAGE + ASZ*NBUF;
        bf16* Bl = Bh + BSZE;
        #pragma unroll
        for (int l = 0; l < BCHUNK; l++) {
            int i = tid + l*NT;
            int r = i/(BK/8), q = i%(BK/8);
            CP_ASYNC16(sptr(&Bh[r*LDA + q*8]), &BT_hi[(size_t)(n0+r)*K + kt*BK + q*8]);
            if (PASSES > 1)
                CP_ASYNC16(sptr(&Bl[r*LDA + q*8]), &BT_lo[(size_t)(n0+r)*K + kt*BK + q*8]);
        }
    };

    ldA(0); ldB(0, 0); CP_COMMIT(); stA(0);
    CP_WAIT0(); __syncthreads();

    for (int kt = 0; kt < KT; kt++) {
        int s = kt & 1;
        bool nxt = (kt + 1 < KT);
        if (nxt) { ldB(s^1, kt+1); CP_COMMIT(); ldA(kt+1); }

        uint32_t ahb = sptr(sm + s*STAGE) + (uint32_t)(wm*MF*16*LDA*2) + a_off;
        uint32_t alb = ahb + (uint32_t)(ASZ*2);
        uint32_t bhb = sptr(sm + s*STAGE + ASZ*NBUF) + (uint32_t)(wn*NF*8*LDA*2) + b_off;
        uint32_t blb = bhb + (uint32_t)(BSZE*2);
        #pragma unroll
        for (int k0 = 0; k0 < BK; k0 += 16) {
            uint32_t ah[MF][4], al[MF][4];
            #pragma unroll
            for (int mf = 0; mf < MF; mf++) {
                LDSM_X4(ah[mf], ahb + (uint32_t)((mf*16*LDA + k0)*2));
                if (PASSES > 1)
                    LDSM_X4(al[mf], alb + (uint32_t)((mf*16*LDA + k0)*2));
            }
            #pragma unroll
            for (int np = 0; np < NF/2; np++) {
                uint32_t bh[4];
                LDSM_X4(bh, bhb + (uint32_t)((np*16*LDA + k0)*2));
                #pragma unroll
                for (int mf = 0; mf < MF; mf++) {
                    mma_bf16(c[mf][2*np],   ah[mf], bh[0], bh[1]);
                    mma_bf16(c[mf][2*np+1], ah[mf], bh[2], bh[3]);
                }
                if (PASSES > 1) {
                    uint32_t bl[4];
                    LDSM_X4(bl, blb + (uint32_t)((np*16*LDA + k0)*2));
                    #pragma unroll
                    for (int mf = 0; mf < MF; mf++) {
                        mma_bf16(c[mf][2*np],   al[mf], bh[0], bh[1]);
                        mma_bf16(c[mf][2*np+1], al[mf], bh[2], bh[3]);
                        mma_bf16(c[mf][2*np],   ah[mf], bl[0], bl[1]);
                        mma_bf16(c[mf][2*np+1], ah[mf], bl[2], bl[3]);
                    }
                }
            }
        }
        if (nxt) stA(s^1);
        CP_WAIT0(); __syncthreads();
    }

    int mc = OUTM ? memcnt[0] : 0;
    #pragma unroll
    for (int mf = 0; mf < MF; mf++) {
        int r0 = m0 + wm*MF*16 + mf*16 + g;
        #pragma unroll
        for (int nf = 0; nf < NF; nf++) {
            int cb = n0 + wn*NF*8 + nf*8 + 2*tg;
            float v0 = c[mf][nf][0] + bias[cb];
            float v1 = c[mf][nf][1] + bias[cb+1];
            float v2 = c[mf][nf][2] + bias[cb];
            float v3 = c[mf][nf][3] + bias[cb+1];
            if (OUTM) {
                int row0 = (mc < MS) ? mc : g_idx[r0];
                int row1 = (mc < MS) ? mc : g_idx[r0+8];
                float* d0 = &C[((size_t)r0*MS + row0)*RS];
                float* d1 = &C[((size_t)(r0+8)*MS + row1)*RS];
                d0[cb] = v0; d0[cb+1] = v1;
                d1[cb] = v2; d1[cb+1] = v3;
            } else {
                C[(size_t)r0*N + cb]       = v0;
                C[(size_t)r0*N + cb + 1]   = v1;
                C[(size_t)(r0+8)*N + cb]   = v2;
                C[(size_t)(r0+8)*N + cb+1] = v3;
            }
        }
    }
}

// ---------------- k_hid_mma: copy removed; MMA + head + argmax + r + ab ----------------
__global__ __launch_bounds__(256) void k_hid_mma(
    const float* __restrict__ hmem,
    const float* __restrict__ prev, const float* __restrict__ nsm,
    const float* __restrict__ x, const float* __restrict__ h,
    const float* __restrict__ W1, const float* __restrict__ b1,
    const float* __restrict__ nsig, float* __restrict__ d_out) {
    constexpr int LDA = 72;
    __shared__ __align__(16) bf16 As_hi[128*LDA];
    __shared__ __align__(16) bf16 Bs_hi[128*LDA];
    __shared__ float s_base[128], s_veca[128], s_head[128];
    __shared__ float red[256], red1[256];
    __shared__ float sv[128];
    __shared__ int   si[128];
    __shared__ float sh_r[64];
    int tid = threadIdx.x;
    int w = tid >> 5, lane = tid & 31, g = lane >> 2, tg = lane & 3;
    int wm = w >> 2, wn = w & 3;
    int b = blockIdx.x;

    const float4* src = (const float4*)(hmem + (size_t)b*8192);
    for (int i = tid; i < 2048; i += 256) {
        float4 v = src[i];
        int row = i >> 4, c4 = (i & 15) * 4;
        uint2 hh; hh.x = pack_hi2(v.x, v.y); hh.y = pack_hi2(v.z, v.w);
        *(uint2*)&As_hi[row*LDA + c4] = hh;
    }
    for (int i = tid; i < 1024; i += 256) {
        int r = i >> 3, q = i & 7;
        *(uint4*)&Bs_hi[r*LDA + q*8] = *(const uint4*)&g_Wm_hi[r*64 + q*8];
    }
    if (tid < 128) {
        s_base[tid] = g_base[(size_t)b*128 + tid];
        s_veca[tid] = g_veca[tid];
        s_head[tid] = 0.f;
    }
    __syncthreads();

    uint32_t a_lane_off = (uint32_t)(((((lane>>3)&1)*8 + (lane&7))*LDA + (lane>>4)*8) * 2);
    uint32_t as_base = sptr(As_hi) + (uint32_t)(wm*64*LDA*2) + a_lane_off;

    float c[4][4][4] = {};
    #pragma unroll
    for (int k0 = 0; k0 < 64; k0 += 16) {
        uint32_t ah[4][4];
        #pragma unroll
        for (int mf = 0; mf < 4; mf++)
            LDSM_X4(ah[mf], as_base + (uint32_t)((mf*16*LDA + k0)*2));
        #pragma unroll
        for (int nf = 0; nf < 4; nf++) {
            int nb = wn*32 + nf*8 + g;
            uint32_t bh0 = *(uint32_t*)&Bs_hi[nb*LDA + k0 + 2*tg];
            uint32_t bh1 = *(uint32_t*)&Bs_hi[nb*LDA + k0 + 8 + 2*tg];
            #pragma unroll
            for (int mf = 0; mf < 4; mf++) mma_bf16(c[mf][nf], ah[mf], bh0, bh1);
        }
    }

    #pragma unroll
    for (int mf = 0; mf < 4; mf++) {
        int r0 = wm*64 + mf*16 + g, r1 = r0 + 8;
        float hs0 = 0.f, hs1 = 0.f;
        #pragma unroll
        for (int nf = 0; nf < 4; nf++) {
            int cb = wn*32 + nf*8 + 2*tg;
            float v;
            v = c[mf][nf][0] + s_base[cb]   + g_keyW[r0*128 + cb];   hs0 += tanh_fast(v)*s_veca[cb];
            v = c[mf][nf][1] + s_base[cb+1] + g_keyW[r0*128 + cb+1]; hs0 += tanh_fast(v)*s_veca[cb+1];
            v = c[mf][nf][2] + s_base[cb]   + g_keyW[r1*128 + cb];   hs1 += tanh_fast(v)*s_veca[cb];
            v = c[mf][nf][3] + s_base[cb+1] + g_keyW[r1*128 + cb+1]; hs1 += tanh_fast(v)*s_veca[cb+1];
        }
        atomicAdd(&s_head[r0], hs0);
        atomicAdd(&s_head[r1], hs1);
    }
    __syncthreads();

    int t = tid;
    float val = 0.f;
    if (t < 128) {
        val = s_head[t] - 100.f * prev[b*128 + t];
        red[t] = val * val;
    }
    __syncthreads();
    if (t < 64) red[t] += red[t+64];
    __syncthreads();
    for (int s = 32; s > 0; s >>= 1) { if (t < s) red[t] += red[t+s]; __syncthreads(); }
    if (t < 128) {
        float norm = fmaxf(sqrtf(red[0]), 1e-12f);
        sv[t] = val / norm + gumbel(nsm[b*128 + t]);
        si[t] = t;
    }
    __syncthreads();
    for (int s = 64; s > 0; s >>= 1) {
        if (t < s && sv[t+s] > sv[t]) { sv[t] = sv[t+s]; si[t] = si[t+s]; }
        __syncthreads();
    }
    int best = si[0];
    if (t == 0) g_idx[b] = best;
    if (t < 64) {
        float rv = hmem[((size_t)b*128 + best)*64 + t];
        g_r[b*64 + t] = rv;
        sh_r[t] = rv;
        d_out[(size_t)b*OC + 512 + t] = rv;
    }
    __syncthreads();
    float s0 = 0.f, s1 = 0.f;
    for (int k = t; k < CAT0; k += 256) {
        float a = (k < 256) ? x[b*256+k] : (k < 768) ? h[b*512 + (k-256)] : sh_r[k-768];
        s0 += a * W1[k*2];
        s1 += a * W1[k*2 + 1];
    }
    red[t] = s0; red1[t] = s1;
    __syncthreads();
    for (int s = 128; s > 0; s >>= 1) {
        if (t < s) { red[t] += red[t+s]; red1[t] += red1[t+s]; }
        __syncthreads();
    }
    if (t == 0) {
        const float ST = (float)(10.0/3.0);
        g_ab[b*2]     = sigm((red[0]  + b1[0] + gumbel(nsig[b*2]))   * ST);
        g_ab[b*2 + 1] = sigm((red1[0] + b1[1] + gumbel(nsig[b*2+1])) * ST);
    }
}

// ---------------- k_ep ----------------
__global__ void k_ep(const float* __restrict__ c, float* __restrict__ d_out) {
    int gid = blockIdx.x * blockDim.x + threadIdx.x;
    int b = gid >> 9, j = gid & 511;
    float i_ = g_G[(size_t)b*GN + j];
    float f_ = g_G[(size_t)b*GN + 512 + j];
    float o_ = g_G[(size_t)b*GN + 1024 + j];
    float p  = g_P[(size_t)b*HS + j];
    float nc = c[gid] * sigm(f_ + 1.f) + sigm(i_) * tanhf(p);
    float nh = tanhf(nc) * sigm(o_);
    d_out[(size_t)b*OC + j] = nh;
}

// ---------------- launch ----------------
extern "C" void kernel_launch(void* const* d_in, const int* in_sizes, int n_in,
                              void* d_out, int out_size) {
    const float* x        = (const float*)d_in[0];
    const float* h        = (const float*)d_in[1];
    const float* c        = (const float*)d_in[2];
    const float* hmem     = (const float*)d_in[3];
    const float* u_t      = (const float*)d_in[4];
    const float* prev     = (const float*)d_in[5];
    const float* W_full   = (const float*)d_in[6];
    const float* bias     = (const float*)d_in[7];
    const float* W_full1  = (const float*)d_in[8];
    const float* bias1    = (const float*)d_in[9];
    const float* W_full2  = (const float*)d_in[10];
    const float* bias2    = (const float*)d_in[11];
    const float* keys     = (const float*)d_in[12];
    const float* vec_a    = (const float*)d_in[13];
    const float* W_fc     = (const float*)d_in[14];
    const float* b_fc     = (const float*)d_in[15];
    const float* W_fc1    = (const float*)d_in[16];
    const float* b_fc1    = (const float*)d_in[17];
    const float* noise_sm = (const float*)d_in[18];
    const float* noise_sig= (const float*)d_in[19];
    const int*   memcnt   = (const int*)d_in[20];

    float* out      = (float*)d_out;
    float* out_hmem = out + (size_t)BSZ * OC;

    float *pbase, *puinv;
    bf16 *pWbh, *pWwh, *pWwl;
    cudaGetSymbolAddress((void**)&pbase, g_base);
    cudaGetSymbolAddress((void**)&puinv, g_uinv);
    cudaGetSymbolAddress((void**)&pWbh,  g_Wb_hi);
    cudaGetSymbolAddress((void**)&pWwh,  g_Ww_hi);
    cudaGetSymbolAddress((void**)&pWwl,  g_Ww_lo);

    auto kBase = mgemm<2,4,1,2, 2,1, 0>;  // 32x64 tile, 1-pass
    auto kHw   = mgemm<2,2,1,4, 3,3, 1>;  // 32x64 tile, 3-pass, hmem scatter
    cudaFuncSetAttribute((const void*)k_gp,  cudaFuncAttributeMaxDynamicSharedMemorySize, GP_SMEM);
    cudaFuncSetAttribute((const void*)kBase, cudaFuncAttributeMaxDynamicSharedMemorySize, 15360);
    cudaFuncSetAttribute((const void*)kHw,   cudaFuncAttributeMaxDynamicSharedMemorySize, 30720);

    // 1. all prep
    k_prep<<<T_ALL, 256>>>(W_full, W_full2, W_fc, W_fc1, keys, vec_a, u_t);
    // 2. base = [x,c,u^]@Wb + b_fc
    kBase<<<dim3(2, BSZ/32), 256, 15360>>>(
        x, c, u_t, puinv, pWbh, pWbh, pbase, b_fc, nullptr, 128, XCU);
    // 3. hid + head + argmax + r + ab (no copy)
    k_hid_mma<<<BSZ, 256>>>(hmem, prev, noise_sm, x, h, W_full1, bias1, noise_sig, out);
    // 4. merged G + P GEMM + interleaved hmem copy (512 blocks, 2/SM)
    k_gp<<<dim3(GP_NGX + HS/64, BSZ/128), 256, GP_SMEM>>>(x, h, bias, bias2, hmem, out_hmem);
    // 5. LSTM epilogue -> new_h
    k_ep<<<(BSZ*HS)/256, 256>>>(c, out);
    // 6. h_w = [x,new_h]@W_fc1 + b_fc1 -> scatter into out_hmem rows
    kHw<<<dim3(1, BSZ/32), 128, 30720>>>(
        x, out, nullptr, nullptr, pWwh, pWwl, out_hmem, b_fc1, memcnt, 64, 768);
    (void)in_sizes; (void)n_in; (void)out_size;
}